// round 1
// baseline (speedup 1.0000x reference)
#include <cuda_runtime.h>
#include <math.h>

#define B_SZ 32
#define T_SZ 2048
#define D_SZ 1024
#define U_SZ 1024

// scratch (static __device__ — no runtime allocation)
__device__ float g_A[B_SZ * U_SZ];            // q@W1 + b1 + b2
__device__ float g_score[B_SZ * T_SZ];        // raw scores
__device__ float g_cpart[4 * B_SZ * D_SZ];    // context partial sums

typedef unsigned long long u64;

__device__ __forceinline__ u64 pack2(float lo, float hi) {
    u64 r;
    asm("mov.b64 %0, {%1, %2};" : "=l"(r) : "f"(lo), "f"(hi));
    return r;
}
__device__ __forceinline__ void unpack2(u64 v, float& lo, float& hi) {
    asm("mov.b64 {%0, %1}, %2;" : "=f"(lo), "=f"(hi) : "l"(v));
}
// packed dual-FMA (sm_100+): 2 fp32 FMAs per instruction
__device__ __forceinline__ void ffma2(u64& c, u64 a, u64 b) {
    asm("fma.rn.f32x2 %0, %1, %2, %0;" : "+l"(c) : "l"(a), "l"(b));
}
// accurate-enough tanh without MUFU.TANH (abs err ~1e-6)
__device__ __forceinline__ float fast_tanh(float x) {
    float e = __expf(2.0f * x);
    return 1.0f - __fdividef(2.0f, e + 1.0f);
}

// ---------------------------------------------------------------------------
// Kernel 1: A[b,u] = sum_d query[b,d]*W1[d,u] + b1[u] + b2[u]
// ---------------------------------------------------------------------------
__global__ __launch_bounds__(256) void qproj_kernel(
    const float* __restrict__ query, const float* __restrict__ W1,
    const float* __restrict__ b1, const float* __restrict__ b2) {
    __shared__ float qs[D_SZ];
    const int b = blockIdx.y;
    const int u = blockIdx.x * 256 + threadIdx.x;
#pragma unroll
    for (int i = 0; i < 4; i++)
        qs[threadIdx.x + i * 256] = query[b * D_SZ + threadIdx.x + i * 256];
    __syncthreads();
    float a0 = 0.f, a1 = 0.f, a2 = 0.f, a3 = 0.f;
#pragma unroll 4
    for (int d = 0; d < D_SZ; d += 4) {
        a0 += qs[d + 0] * W1[(size_t)(d + 0) * U_SZ + u];
        a1 += qs[d + 1] * W1[(size_t)(d + 1) * U_SZ + u];
        a2 += qs[d + 2] * W1[(size_t)(d + 2) * U_SZ + u];
        a3 += qs[d + 3] * W1[(size_t)(d + 3) * U_SZ + u];
    }
    g_A[b * U_SZ + u] = b1[u] + b2[u] + ((a0 + a1) + (a2 + a3));
}

// ---------------------------------------------------------------------------
// Kernel 2 (dominant): fused GEMM + tanh + Wv-reduction -> scores
// Per block: one b, 128 t-rows, all U in 128-wide chunks, K in 16-wide chunks.
// 256 threads = 16x16 grid; each thread owns an 8(t) x 8(u) micro-tile held as
// 8x4 f32x2 accumulators.
// ---------------------------------------------------------------------------
#define TT 128
#define UC 128
#define KC 16
#define VS_STRIDE 132

__global__ __launch_bounds__(256) void score_kernel(
    const float* __restrict__ values, const float* __restrict__ W2,
    const float* __restrict__ Wv, const float* __restrict__ bvp) {
    __shared__ float Vs[KC][VS_STRIDE];  // [k][t] (transposed values tile)
    __shared__ float Ws[KC][UC];         // [k][u]

    const int tid = threadIdx.x;
    const int tx = tid & 15;   // u-group
    const int ty = tid >> 4;   // t-group
    const int b = blockIdx.y;
    const int t0 = blockIdx.x * TT;

    const float* vbase = values + ((size_t)b * T_SZ + t0) * D_SZ;

    // cooperative-load index maps
    const int vt = tid >> 2;         // 0..63 (t row, +64 for second half)
    const int vk = (tid & 3) * 4;    // k offset within chunk
    const int wk = tid >> 5;         // 0..7 (k row, +8 for second half)
    const int wc = (tid & 31) * 4;   // u offset within chunk

    float s_acc[8];
#pragma unroll
    for (int i = 0; i < 8; i++) s_acc[i] = 0.f;

    for (int u0 = 0; u0 < U_SZ; u0 += UC) {
        u64 acc[8][4];
#pragma unroll
        for (int i = 0; i < 8; i++)
#pragma unroll
            for (int j = 0; j < 4; j++) acc[i][j] = 0ull;

        // prefetch chunk 0
        float4 v0 = *(const float4*)(vbase + (size_t)vt * D_SZ + vk);
        float4 v1 = *(const float4*)(vbase + (size_t)(vt + 64) * D_SZ + vk);
        float4 w0 = *(const float4*)(W2 + (size_t)wk * U_SZ + u0 + wc);
        float4 w1 = *(const float4*)(W2 + (size_t)(wk + 8) * U_SZ + u0 + wc);

        for (int k0 = 0; k0 < D_SZ; k0 += KC) {
            __syncthreads();
            // store prefetched chunk (values transposed -> Vs[k][t])
            Vs[vk + 0][vt] = v0.x; Vs[vk + 1][vt] = v0.y;
            Vs[vk + 2][vt] = v0.z; Vs[vk + 3][vt] = v0.w;
            Vs[vk + 0][vt + 64] = v1.x; Vs[vk + 1][vt + 64] = v1.y;
            Vs[vk + 2][vt + 64] = v1.z; Vs[vk + 3][vt + 64] = v1.w;
            *(float4*)&Ws[wk][wc] = w0;
            *(float4*)&Ws[wk + 8][wc] = w1;
            __syncthreads();

            if (k0 + KC < D_SZ) {  // prefetch next chunk
                v0 = *(const float4*)(vbase + (size_t)vt * D_SZ + k0 + KC + vk);
                v1 = *(const float4*)(vbase + (size_t)(vt + 64) * D_SZ + k0 + KC + vk);
                w0 = *(const float4*)(W2 + (size_t)(k0 + KC + wk) * U_SZ + u0 + wc);
                w1 = *(const float4*)(W2 + (size_t)(k0 + KC + wk + 8) * U_SZ + u0 + wc);
            }

#pragma unroll
            for (int k = 0; k < KC; k++) {
                const float4 bA = *(const float4*)&Ws[k][tx * 8];
                const float4 bB = *(const float4*)&Ws[k][tx * 8 + 4];
                const u64 b01 = pack2(bA.x, bA.y);
                const u64 b23 = pack2(bA.z, bA.w);
                const u64 b45 = pack2(bB.x, bB.y);
                const u64 b67 = pack2(bB.z, bB.w);
                const float4 aA = *(const float4*)&Vs[k][ty * 8];
                const float4 aB = *(const float4*)&Vs[k][ty * 8 + 4];
                const float av[8] = {aA.x, aA.y, aA.z, aA.w,
                                     aB.x, aB.y, aB.z, aB.w};
#pragma unroll
                for (int i = 0; i < 8; i++) {
                    const u64 a2 = pack2(av[i], av[i]);
                    ffma2(acc[i][0], a2, b01);
                    ffma2(acc[i][1], a2, b23);
                    ffma2(acc[i][2], a2, b45);
                    ffma2(acc[i][3], a2, b67);
                }
            }
        }

        // epilogue: h = tanh(A[b,u] + vproj); s += Wv[u]*h
#pragma unroll
        for (int jp = 0; jp < 4; jp++) {
            const int u = u0 + tx * 8 + jp * 2;
            const float A0 = g_A[b * U_SZ + u];
            const float A1 = g_A[b * U_SZ + u + 1];
            const float wv0 = Wv[u];
            const float wv1 = Wv[u + 1];
#pragma unroll
            for (int i = 0; i < 8; i++) {
                float lo, hi;
                unpack2(acc[i][jp], lo, hi);
                s_acc[i] += wv0 * fast_tanh(A0 + lo) + wv1 * fast_tanh(A1 + hi);
            }
        }
    }

    // reduce over the 16 u-thread-groups (16-lane shuffle segments)
    const float bv0 = bvp[0];
#pragma unroll
    for (int i = 0; i < 8; i++) {
        float v = s_acc[i];
        v += __shfl_down_sync(0xffffffffu, v, 8, 16);
        v += __shfl_down_sync(0xffffffffu, v, 4, 16);
        v += __shfl_down_sync(0xffffffffu, v, 2, 16);
        v += __shfl_down_sync(0xffffffffu, v, 1, 16);
        if (tx == 0) g_score[b * T_SZ + t0 + ty * 8 + i] = v + bv0;
    }
}

// ---------------------------------------------------------------------------
// Kernel 3: softmax over T per batch; writes attention weights to output
// ---------------------------------------------------------------------------
__global__ __launch_bounds__(256) void softmax_kernel(float* __restrict__ wout) {
    __shared__ float red[256];
    const int b = blockIdx.x;
    const int tid = threadIdx.x;
    const float* s = g_score + b * T_SZ;
    float* w = wout + b * T_SZ;

    float m = -3.4e38f;
    for (int t = tid; t < T_SZ; t += 256) m = fmaxf(m, s[t]);
    red[tid] = m;
    __syncthreads();
    for (int o = 128; o > 0; o >>= 1) {
        if (tid < o) red[tid] = fmaxf(red[tid], red[tid + o]);
        __syncthreads();
    }
    const float mx = red[0];
    __syncthreads();

    float sum = 0.f;
    for (int t = tid; t < T_SZ; t += 256) {
        float e = __expf(s[t] - mx);
        w[t] = e;
        sum += e;
    }
    red[tid] = sum;
    __syncthreads();
    for (int o = 128; o > 0; o >>= 1) {
        if (tid < o) red[tid] += red[tid + o];
        __syncthreads();
    }
    const float inv = 1.0f / red[0];
    for (int t = tid; t < T_SZ; t += 256) w[t] *= inv;
}

// ---------------------------------------------------------------------------
// Kernel 4: context[b,d] = sum_t w[b,t]*values[b,t,d], t split 4-way (no atomics)
// ---------------------------------------------------------------------------
__global__ __launch_bounds__(256) void context_part_kernel(
    const float* __restrict__ values, const float* __restrict__ w) {
    __shared__ float wsh[512];
    const int b = blockIdx.y;
    const int z = blockIdx.z;
    const int d = blockIdx.x * 256 + threadIdx.x;
    const int t0 = z * 512;
    for (int i = threadIdx.x; i < 512; i += 256) wsh[i] = w[b * T_SZ + t0 + i];
    __syncthreads();
    const float* vb = values + ((size_t)b * T_SZ + t0) * D_SZ + d;
    float a0 = 0.f, a1 = 0.f, a2 = 0.f, a3 = 0.f;
#pragma unroll 4
    for (int t = 0; t < 512; t += 4) {
        a0 += wsh[t + 0] * vb[(size_t)(t + 0) * D_SZ];
        a1 += wsh[t + 1] * vb[(size_t)(t + 1) * D_SZ];
        a2 += wsh[t + 2] * vb[(size_t)(t + 2) * D_SZ];
        a3 += wsh[t + 3] * vb[(size_t)(t + 3) * D_SZ];
    }
    g_cpart[((size_t)z * B_SZ + b) * D_SZ + d] = (a0 + a1) + (a2 + a3);
}

__global__ void context_reduce_kernel(float* __restrict__ out) {
    const int b = blockIdx.x;
    const int d = threadIdx.x;  // 1024 threads
    float s = 0.f;
#pragma unroll
    for (int z = 0; z < 4; z++) s += g_cpart[((size_t)z * B_SZ + b) * D_SZ + d];
    out[b * D_SZ + d] = s;
}

// ---------------------------------------------------------------------------
extern "C" void kernel_launch(void* const* d_in, const int* in_sizes, int n_in,
                              void* d_out, int out_size) {
    const float* query  = (const float*)d_in[0];
    const float* values = (const float*)d_in[1];
    const float* W1     = (const float*)d_in[2];
    const float* b1     = (const float*)d_in[3];
    const float* W2     = (const float*)d_in[4];
    const float* b2     = (const float*)d_in[5];
    const float* Wv     = (const float*)d_in[6];
    const float* bv     = (const float*)d_in[7];

    float* out = (float*)d_out;
    float* ctx_out = out;                  // [B, D]    = 32768 floats
    float* w_out   = out + B_SZ * D_SZ;    // [B, T, 1] = 65536 floats

    qproj_kernel<<<dim3(4, B_SZ), 256>>>(query, W1, b1, b2);
    score_kernel<<<dim3(T_SZ / TT, B_SZ), 256>>>(values, W2, Wv, bv);
    softmax_kernel<<<B_SZ, 256>>>(w_out);
    context_part_kernel<<<dim3(4, B_SZ, 4), 256>>>(values, w_out);
    context_reduce_kernel<<<B_SZ, 1024>>>(ctx_out);
}

// round 3
// speedup vs baseline: 2.1439x; 2.1439x over previous
#include <cuda_runtime.h>
#include <cuda_bf16.h>
#include <cstdint>
#include <math.h>

#define B_SZ 32
#define T_SZ 2048
#define D_SZ 1024
#define U_SZ 1024

typedef unsigned long long u64;

// ---------------- static device scratch (no runtime allocation) -------------
__device__ float g_A[B_SZ * U_SZ];              // q@W1 + b1 + b2
__device__ float g_score[B_SZ * T_SZ];          // raw scores
__device__ float g_cpart[4 * B_SZ * D_SZ];      // context partials
__device__ __nv_bfloat16 g_W2t_hi[U_SZ * D_SZ]; // W2^T split hi  [u][d]
__device__ __nv_bfloat16 g_W2t_lo[U_SZ * D_SZ]; // W2^T split lo  [u][d]

__device__ __forceinline__ float fast_tanh(float x) {
    float e = __expf(2.0f * x);
    return 1.0f - __fdividef(2.0f, e + 1.0f);
}

// fp32x4 -> (bf16x4 hi, bf16x4 lo) packed as u64s
__device__ __forceinline__ void cvt4(const float4 v, u64& hi, u64& lo) {
    __nv_bfloat16 h0 = __float2bfloat16_rn(v.x), h1 = __float2bfloat16_rn(v.y);
    __nv_bfloat16 h2 = __float2bfloat16_rn(v.z), h3 = __float2bfloat16_rn(v.w);
    __nv_bfloat16 l0 = __float2bfloat16_rn(v.x - __bfloat162float(h0));
    __nv_bfloat16 l1 = __float2bfloat16_rn(v.y - __bfloat162float(h1));
    __nv_bfloat16 l2 = __float2bfloat16_rn(v.z - __bfloat162float(h2));
    __nv_bfloat16 l3 = __float2bfloat16_rn(v.w - __bfloat162float(h3));
    __nv_bfloat162 ph01 = __halves2bfloat162(h0, h1), ph23 = __halves2bfloat162(h2, h3);
    __nv_bfloat162 pl01 = __halves2bfloat162(l0, l1), pl23 = __halves2bfloat162(l2, l3);
    hi = ((u64)(*(unsigned*)&ph23) << 32) | (*(unsigned*)&ph01);
    lo = ((u64)(*(unsigned*)&pl23) << 32) | (*(unsigned*)&pl01);
}

// warp-level bf16 tensor-core MMA (arch-portable PTX, runs on HMMA pipe)
#define MMA16816(d, a, b0, b1)                                              \
    asm volatile(                                                           \
        "mma.sync.aligned.m16n8k16.row.col.f32.bf16.bf16.f32 "              \
        "{%0,%1,%2,%3}, {%4,%5,%6,%7}, {%8,%9}, {%0,%1,%2,%3};"             \
        : "+f"((d)[0]), "+f"((d)[1]), "+f"((d)[2]), "+f"((d)[3])            \
        : "r"((a)[0]), "r"((a)[1]), "r"((a)[2]), "r"((a)[3]),               \
          "r"(b0), "r"(b1))

// ---------------------------------------------------------------------------
// Kernel 0: W2 -> transposed bf16 hi/lo split  (W2t[u][d])
// ---------------------------------------------------------------------------
__global__ __launch_bounds__(256) void w2t_prep_kernel(const float* __restrict__ W2) {
    const int u = blockIdx.x;
    for (int d = threadIdx.x; d < D_SZ; d += 256) {
        float x = W2[(size_t)d * U_SZ + u];
        __nv_bfloat16 h = __float2bfloat16_rn(x);
        __nv_bfloat16 l = __float2bfloat16_rn(x - __bfloat162float(h));
        g_W2t_hi[(size_t)u * D_SZ + d] = h;
        g_W2t_lo[(size_t)u * D_SZ + d] = l;
    }
}

// ---------------------------------------------------------------------------
// Kernel 1: A[b,u] = q@W1 + b1 + b2
// ---------------------------------------------------------------------------
__global__ __launch_bounds__(256) void qproj_kernel(
    const float* __restrict__ query, const float* __restrict__ W1,
    const float* __restrict__ b1, const float* __restrict__ b2) {
    __shared__ float qs[D_SZ];
    const int b = blockIdx.y;
    const int u = blockIdx.x * 256 + threadIdx.x;
#pragma unroll
    for (int i = 0; i < 4; i++)
        qs[threadIdx.x + i * 256] = query[b * D_SZ + threadIdx.x + i * 256];
    __syncthreads();
    float a0 = 0.f, a1 = 0.f, a2 = 0.f, a3 = 0.f;
#pragma unroll 4
    for (int d = 0; d < D_SZ; d += 4) {
        a0 += qs[d + 0] * W1[(size_t)(d + 0) * U_SZ + u];
        a1 += qs[d + 1] * W1[(size_t)(d + 1) * U_SZ + u];
        a2 += qs[d + 2] * W1[(size_t)(d + 2) * U_SZ + u];
        a3 += qs[d + 3] * W1[(size_t)(d + 3) * U_SZ + u];
    }
    g_A[b * U_SZ + u] = b1[u] + b2[u] + ((a0 + a1) + (a2 + a3));
}

// ---------------------------------------------------------------------------
// Kernel 2 (dominant): bf16 3-split mma.sync GEMM + tanh + Wv reduce -> scores
// CTA: one b, 256 t-rows. 512 threads = 16 warps (8 m-groups x 2 n-groups).
// u-passes of 128 (x8); K chunks of 32, double-buffered smem.
// ---------------------------------------------------------------------------
#define TT 256
#define UC 128
#define KC 32
#define NCHUNK (D_SZ / KC)
#define NPASS (U_SZ / UC)
#define APITCH 80                      // bytes per smem row (40 halves, pad 8)
#define OFF_ALO (TT * APITCH)          // 20480
#define OFF_BHI (2 * TT * APITCH)      // 40960
#define OFF_BLO (OFF_BHI + UC * APITCH)// 51200
#define STAGE (OFF_BLO + UC * APITCH)  // 61440
#define EX (2 * STAGE)                 // 122880
#define SMEM_BYTES (EX + 1024 + 2048)

__global__ __launch_bounds__(512, 1) void score_mma_kernel(
    const float* __restrict__ values, const float* __restrict__ Wv,
    const float* __restrict__ bvp) {
    extern __shared__ char sm[];
    float2* sAWv = (float2*)(sm + EX);             // 128 (A, Wv) pairs
    float(*sred)[TT] = (float(*)[TT])(sm + EX + 1024);

    const int tid = threadIdx.x;
    const int wid = tid >> 5;
    const int lane = tid & 31;
    const int b = blockIdx.y;
    const int t0 = blockIdx.x * TT;

    const int m0 = (wid & 7) * 32;     // warp m-origin (t)
    const int wn = wid >> 3;           // warp n-group
    const int n0 = wn * 64;            // warp n-origin (u, within chunk)

    const float* vbase = values + ((size_t)b * T_SZ + t0) * D_SZ;

    // gmem load maps
    const int ar0 = tid >> 3;          // A: base row (0..63), rows ar0+64*i
    const int ac4 = tid & 7;           // A: float4 index within 32-float row
    const int brow = tid >> 2;         // B: row (0..127)
    const int bq = tid & 3;            // B: uint4 index within row

    // fragment maps
    const int fr = lane >> 2;          // fragment row within 8
    const int fc = (lane & 3) * 2;     // fragment k-pair / n-pair origin

    float s_part[4] = {0.f, 0.f, 0.f, 0.f};

    for (int p = 0; p < NPASS; p++) {
        const int u0 = p * UC;
        __syncthreads();               // previous epilogue done before sAWv overwrite
        if (tid < UC) sAWv[tid] = make_float2(g_A[b * U_SZ + u0 + tid], Wv[u0 + tid]);

        float acc[2][8][4];
#pragma unroll
        for (int mt = 0; mt < 2; mt++)
#pragma unroll
            for (int nt = 0; nt < 8; nt++)
#pragma unroll
                for (int ci = 0; ci < 4; ci++) acc[mt][nt][ci] = 0.f;

        const __nv_bfloat16* bhp = g_W2t_hi + (size_t)(u0 + brow) * D_SZ + bq * 8;
        const __nv_bfloat16* blp = g_W2t_lo + (size_t)(u0 + brow) * D_SZ + bq * 8;

        // ---- prologue: chunk 0
        u64 avhi[4], avlo[4];
        uint4 rbh, rbl;
#pragma unroll
        for (int i = 0; i < 4; i++) {
            float4 v = *(const float4*)(vbase + (size_t)(ar0 + 64 * i) * D_SZ + ac4 * 4);
            cvt4(v, avhi[i], avlo[i]);
        }
        rbh = *(const uint4*)bhp;
        rbl = *(const uint4*)blp;
        {
            char* sb = sm;             // stage 0
#pragma unroll
            for (int i = 0; i < 4; i++) {
                const int off = (ar0 + 64 * i) * APITCH + ac4 * 8;
                *(u64*)(sb + off) = avhi[i];
                *(u64*)(sb + OFF_ALO + off) = avlo[i];
            }
            const int boff = brow * APITCH + bq * 16;
            *(uint4*)(sb + OFF_BHI + boff) = rbh;
            *(uint4*)(sb + OFF_BLO + boff) = rbl;
        }
        __syncthreads();

#pragma unroll 1
        for (int c = 0; c < NCHUNK; c++) {
            // ---- prefetch chunk c+1 (LDG in flight during MMA)
            if (c + 1 < NCHUNK) {
                const int kc = (c + 1) * KC;
#pragma unroll
                for (int i = 0; i < 4; i++) {
                    float4 v = *(const float4*)(vbase + (size_t)(ar0 + 64 * i) * D_SZ + kc + ac4 * 4);
                    cvt4(v, avhi[i], avlo[i]);
                }
                rbh = *(const uint4*)(bhp + kc);
                rbl = *(const uint4*)(blp + kc);
            }

            // ---- MMA on stage c&1
            {
                const char* sb = sm + (c & 1) * STAGE;
#pragma unroll
                for (int ks = 0; ks < 2; ks++) {
                    const int kb = (ks * 16 + fc) * 2;  // byte offset of k-pair
                    uint32_t ah[2][4], al[2][4];
#pragma unroll
                    for (int mt = 0; mt < 2; mt++) {
                        const char* pa = sb + (m0 + mt * 16 + fr) * APITCH + kb;
                        ah[mt][0] = *(const uint32_t*)(pa);
                        ah[mt][1] = *(const uint32_t*)(pa + 8 * APITCH);
                        ah[mt][2] = *(const uint32_t*)(pa + 16);
                        ah[mt][3] = *(const uint32_t*)(pa + 8 * APITCH + 16);
                        const char* pl = pa + OFF_ALO;
                        al[mt][0] = *(const uint32_t*)(pl);
                        al[mt][1] = *(const uint32_t*)(pl + 8 * APITCH);
                        al[mt][2] = *(const uint32_t*)(pl + 16);
                        al[mt][3] = *(const uint32_t*)(pl + 8 * APITCH + 16);
                    }
#pragma unroll
                    for (int nt = 0; nt < 8; nt++) {
                        const char* pb = sb + OFF_BHI + (n0 + nt * 8 + fr) * APITCH + kb;
                        const uint32_t bh0 = *(const uint32_t*)(pb);
                        const uint32_t bh1 = *(const uint32_t*)(pb + 16);
                        const char* pb2 = pb + (OFF_BLO - OFF_BHI);
                        const uint32_t bl0 = *(const uint32_t*)(pb2);
                        const uint32_t bl1 = *(const uint32_t*)(pb2 + 16);
#pragma unroll
                        for (int mt = 0; mt < 2; mt++) {
                            MMA16816(acc[mt][nt], ah[mt], bh0, bh1);
                            MMA16816(acc[mt][nt], ah[mt], bl0, bl1);
                            MMA16816(acc[mt][nt], al[mt], bh0, bh1);
                        }
                    }
                }
            }
            __syncthreads();           // all warps done reading stage c&1

            // ---- store chunk c+1 into stage (c+1)&1
            if (c + 1 < NCHUNK) {
                char* sb = sm + ((c + 1) & 1) * STAGE;
#pragma unroll
                for (int i = 0; i < 4; i++) {
                    const int off = (ar0 + 64 * i) * APITCH + ac4 * 8;
                    *(u64*)(sb + off) = avhi[i];
                    *(u64*)(sb + OFF_ALO + off) = avlo[i];
                }
                const int boff = brow * APITCH + bq * 16;
                *(uint4*)(sb + OFF_BHI + boff) = rbh;
                *(uint4*)(sb + OFF_BLO + boff) = rbl;
                __syncthreads();
            }
        }

        // ---- epilogue: tanh + Wv partial reduce into per-row s_part
#pragma unroll
        for (int mt = 0; mt < 2; mt++)
#pragma unroll
            for (int h2 = 0; h2 < 2; h2++) {
                const int sp = mt * 2 + h2;
                float accr = 0.f;
#pragma unroll
                for (int nt = 0; nt < 8; nt++) {
                    const int cl = n0 + nt * 8 + fc;
                    const float2 aw0 = sAWv[cl];
                    const float2 aw1 = sAWv[cl + 1];
                    accr += aw0.y * fast_tanh(acc[mt][nt][h2 * 2 + 0] + aw0.x);
                    accr += aw1.y * fast_tanh(acc[mt][nt][h2 * 2 + 1] + aw1.x);
                }
                s_part[sp] += accr;
            }
    }

    // ---- reduce quads (lanes sharing a row) then across the 2 n-warps
#pragma unroll
    for (int sp = 0; sp < 4; sp++) {
        float v = s_part[sp];
        v += __shfl_xor_sync(0xffffffffu, v, 1);
        v += __shfl_xor_sync(0xffffffffu, v, 2);
        if ((lane & 3) == 0) sred[wn][m0 + sp * 8 + fr] = v;
    }
    __syncthreads();
    if (tid < TT)
        g_score[b * T_SZ + t0 + tid] = sred[0][tid] + sred[1][tid] + bvp[0];
}

// ---------------------------------------------------------------------------
// Kernel 3: softmax over T per batch -> attention weights
// ---------------------------------------------------------------------------
__global__ __launch_bounds__(256) void softmax_kernel(float* __restrict__ wout) {
    __shared__ float red[256];
    const int b = blockIdx.x;
    const int tid = threadIdx.x;
    const float* s = g_score + b * T_SZ;
    float* w = wout + b * T_SZ;

    float m = -3.4e38f;
    for (int t = tid; t < T_SZ; t += 256) m = fmaxf(m, s[t]);
    red[tid] = m;
    __syncthreads();
    for (int o = 128; o > 0; o >>= 1) {
        if (tid < o) red[tid] = fmaxf(red[tid], red[tid + o]);
        __syncthreads();
    }
    const float mx = red[0];
    __syncthreads();

    float sum = 0.f;
    for (int t = tid; t < T_SZ; t += 256) {
        float e = __expf(s[t] - mx);
        w[t] = e;
        sum += e;
    }
    red[tid] = sum;
    __syncthreads();
    for (int o = 128; o > 0; o >>= 1) {
        if (tid < o) red[tid] += red[tid + o];
        __syncthreads();
    }
    const float inv = 1.0f / red[0];
    for (int t = tid; t < T_SZ; t += 256) w[t] *= inv;
}

// ---------------------------------------------------------------------------
// Kernel 4/5: context = sum_t w*values  (t split 4-way, deterministic reduce)
// ---------------------------------------------------------------------------
__global__ __launch_bounds__(256) void context_part_kernel(
    const float* __restrict__ values, const float* __restrict__ w) {
    __shared__ float wsh[512];
    const int b = blockIdx.y;
    const int z = blockIdx.z;
    const int d = blockIdx.x * 256 + threadIdx.x;
    const int t0 = z * 512;
    for (int i = threadIdx.x; i < 512; i += 256) wsh[i] = w[b * T_SZ + t0 + i];
    __syncthreads();
    const float* vb = values + ((size_t)b * T_SZ + t0) * D_SZ + d;
    float a0 = 0.f, a1 = 0.f, a2 = 0.f, a3 = 0.f;
#pragma unroll 4
    for (int t = 0; t < 512; t += 4) {
        a0 += wsh[t + 0] * vb[(size_t)(t + 0) * D_SZ];
        a1 += wsh[t + 1] * vb[(size_t)(t + 1) * D_SZ];
        a2 += wsh[t + 2] * vb[(size_t)(t + 2) * D_SZ];
        a3 += wsh[t + 3] * vb[(size_t)(t + 3) * D_SZ];
    }
    g_cpart[((size_t)z * B_SZ + b) * D_SZ + d] = (a0 + a1) + (a2 + a3);
}

__global__ void context_reduce_kernel(float* __restrict__ out) {
    const int b = blockIdx.x;
    const int d = threadIdx.x;
    float s = 0.f;
#pragma unroll
    for (int z = 0; z < 4; z++) s += g_cpart[((size_t)z * B_SZ + b) * D_SZ + d];
    out[b * D_SZ + d] = s;
}

// ---------------------------------------------------------------------------
extern "C" void kernel_launch(void* const* d_in, const int* in_sizes, int n_in,
                              void* d_out, int out_size) {
    const float* query  = (const float*)d_in[0];
    const float* values = (const float*)d_in[1];
    const float* W1     = (const float*)d_in[2];
    const float* b1     = (const float*)d_in[3];
    const float* W2     = (const float*)d_in[4];
    const float* b2     = (const float*)d_in[5];
    const float* Wv     = (const float*)d_in[6];
    const float* bv     = (const float*)d_in[7];

    float* out = (float*)d_out;
    float* ctx_out = out;                  // [B, D]
    float* w_out   = out + B_SZ * D_SZ;    // [B, T, 1]

    static int smem_set = 0;
    if (!smem_set) {
        cudaFuncSetAttribute(score_mma_kernel,
                             cudaFuncAttributeMaxDynamicSharedMemorySize, SMEM_BYTES);
        smem_set = 1;
    }

    w2t_prep_kernel<<<U_SZ, 256>>>(W2);
    qproj_kernel<<<dim3(4, B_SZ), 256>>>(query, W1, b1, b2);
    score_mma_kernel<<<dim3(T_SZ / TT, B_SZ), 512, SMEM_BYTES>>>(values, Wv, bv);
    softmax_kernel<<<B_SZ, 256>>>(w_out);
    context_part_kernel<<<dim3(4, B_SZ, 4), 256>>>(values, w_out);
    context_reduce_kernel<<<B_SZ, 1024>>>(ctx_out);
}

// round 4
// speedup vs baseline: 3.8532x; 1.7973x over previous
#include <cuda_runtime.h>
#include <cuda_fp16.h>
#include <cstdint>
#include <math.h>

#define B_SZ 32
#define T_SZ 2048
#define D_SZ 1024
#define U_SZ 1024

typedef unsigned long long u64;

// ---------------- static device scratch (no runtime allocation) -------------
__device__ float g_A[B_SZ * U_SZ];               // q@W1 + b1 + b2
__device__ float g_score[B_SZ * T_SZ];           // raw scores
__device__ float g_cpart[4 * B_SZ * D_SZ];       // context partials
__device__ __half g_W2t_hi[U_SZ * D_SZ];         // (32*W2)^T fp16 hi [u][d]
__device__ __half g_W2t_lo[U_SZ * D_SZ];         // (32*W2)^T fp16 lo [u][d]
__device__ __half g_vh[67108864];                // values as fp16 (B*T*D)

// ---------------- PTX helpers ----------------------------------------------
__device__ __forceinline__ uint32_t smem_u32(const void* p) {
    uint32_t a;
    asm("{ .reg .u64 t; cvta.to.shared.u64 t, %1; cvt.u32.u64 %0, t; }"
        : "=r"(a) : "l"(p));
    return a;
}
__device__ __forceinline__ float tanh_approx(float x) {
    float y;
    asm("tanh.approx.f32 %0, %1;" : "=f"(y) : "f"(x));
    return y;
}
#define CP16(s, g) \
    asm volatile("cp.async.cg.shared.global [%0], [%1], 16;" :: "r"(s), "l"(g))
#define CP_COMMIT() asm volatile("cp.async.commit_group;" ::: "memory")
#define CP_WAIT(n) asm volatile("cp.async.wait_group %0;" :: "n"(n) : "memory")
#define LDSM4(R0, R1, R2, R3, A) \
    asm volatile("ldmatrix.sync.aligned.m8n8.x4.shared.b16 {%0,%1,%2,%3}, [%4];" \
                 : "=r"(R0), "=r"(R1), "=r"(R2), "=r"(R3) : "r"(A))
#define MMA_F16(d, a, b0, b1)                                               \
    asm volatile(                                                           \
        "mma.sync.aligned.m16n8k16.row.col.f32.f16.f16.f32 "                \
        "{%0,%1,%2,%3}, {%4,%5,%6,%7}, {%8,%9}, {%0,%1,%2,%3};"             \
        : "+f"((d)[0]), "+f"((d)[1]), "+f"((d)[2]), "+f"((d)[3])            \
        : "r"((a)[0]), "r"((a)[1]), "r"((a)[2]), "r"((a)[3]),               \
          "r"(b0), "r"(b1))

// ---------------------------------------------------------------------------
// Kernel P0: values fp32 -> fp16 (one uint4 = 8 halves per thread)
// ---------------------------------------------------------------------------
__global__ __launch_bounds__(256) void vprep_kernel(const float* __restrict__ v) {
    const size_t i8 = (size_t)blockIdx.x * 256 + threadIdx.x;   // uint4 index
    const float4 v0 = ((const float4*)v)[i8 * 2];
    const float4 v1 = ((const float4*)v)[i8 * 2 + 1];
    uint4 o;
    __half2 h;
    h = __floats2half2_rn(v0.x, v0.y); o.x = *(unsigned*)&h;
    h = __floats2half2_rn(v0.z, v0.w); o.y = *(unsigned*)&h;
    h = __floats2half2_rn(v1.x, v1.y); o.z = *(unsigned*)&h;
    h = __floats2half2_rn(v1.z, v1.w); o.w = *(unsigned*)&h;
    ((uint4*)g_vh)[i8] = o;
}

// ---------------------------------------------------------------------------
// Kernel P1: W2 -> transposed, scaled x32, fp16 hi/lo split (tiled transpose)
// ---------------------------------------------------------------------------
__global__ __launch_bounds__(256) void w2t_prep_kernel(const float* __restrict__ W2) {
    __shared__ float tile[32][33];
    const int d0 = blockIdx.x * 32, u0 = blockIdx.y * 32;
    const int tx = threadIdx.x & 31, ty = threadIdx.x >> 5;   // 32 x 8
#pragma unroll
    for (int i = 0; i < 4; i++)
        tile[ty * 4 + i][tx] = W2[(size_t)(d0 + ty * 4 + i) * U_SZ + u0 + tx];
    __syncthreads();
#pragma unroll
    for (int i = 0; i < 4; i++) {
        const int u = u0 + ty * 4 + i;
        float x = tile[tx][ty * 4 + i] * 32.0f;
        __half h = __float2half_rn(x);
        __half l = __float2half_rn(x - __half2float(h));
        g_W2t_hi[(size_t)u * D_SZ + d0 + tx] = h;
        g_W2t_lo[(size_t)u * D_SZ + d0 + tx] = l;
    }
}

// ---------------------------------------------------------------------------
// Kernel 1: A[b,u] = q@W1 + b1 + b2   (fp32, exact)
// ---------------------------------------------------------------------------
__global__ __launch_bounds__(256) void qproj_kernel(
    const float* __restrict__ query, const float* __restrict__ W1,
    const float* __restrict__ b1, const float* __restrict__ b2) {
    __shared__ float qs[D_SZ];
    const int b = blockIdx.y;
    const int u = blockIdx.x * 256 + threadIdx.x;
#pragma unroll
    for (int i = 0; i < 4; i++)
        qs[threadIdx.x + i * 256] = query[b * D_SZ + threadIdx.x + i * 256];
    __syncthreads();
    float a0 = 0.f, a1 = 0.f, a2 = 0.f, a3 = 0.f;
#pragma unroll 4
    for (int d = 0; d < D_SZ; d += 4) {
        a0 += qs[d + 0] * W1[(size_t)(d + 0) * U_SZ + u];
        a1 += qs[d + 1] * W1[(size_t)(d + 1) * U_SZ + u];
        a2 += qs[d + 2] * W1[(size_t)(d + 2) * U_SZ + u];
        a3 += qs[d + 3] * W1[(size_t)(d + 3) * U_SZ + u];
    }
    g_A[b * U_SZ + u] = b1[u] + b2[u] + ((a0 + a1) + (a2 + a3));
}

// ---------------------------------------------------------------------------
// Kernel 2 (dominant): fp16 2-term mma.sync GEMM + tanh + Wv reduce -> scores
// CTA: one b, 256 t-rows; 512 threads = 16 warps (8m x 2n), warp tile 32x64.
// u-passes of 128 (x8); K chunks of 64, double-buffered smem via cp.async.
// D = sum_k vh[t,k] * (32*W2t)[u,k]   (hi+lo), scores use D/32.
// ---------------------------------------------------------------------------
#define TT 256
#define UC 128
#define KC 64
#define NCHUNK (D_SZ / KC)         // 16
#define NPASS (U_SZ / UC)          // 8
#define APITCH 144                 // 64 halves (128B) + 16B pad
#define OFF_BHI (TT * APITCH)      // 36864
#define OFF_BLO (OFF_BHI + UC * APITCH)  // 55296
#define STAGE (OFF_BLO + UC * APITCH)    // 73728
#define EX (2 * STAGE)             // 147456
#define SMEM_BYTES (EX + 1024 + 2048)

__device__ __forceinline__ void issue_chunk(
    uint32_t sbase, const __half* Abase, int u0, int kc, int tid) {
    // A: 256 rows x 64 halves  (4 x 16B per thread)
#pragma unroll
    for (int i = 0; i < 4; i++) {
        const int ch = i * 512 + tid;
        const int r = ch >> 3, col = ch & 7;
        CP16(sbase + r * APITCH + col * 16,
             Abase + (size_t)r * D_SZ + kc + col * 8);
    }
    // B hi/lo: 128 rows x 64 halves each (2 x 16B per thread per array)
#pragma unroll
    for (int i = 0; i < 2; i++) {
        const int ch = i * 512 + tid;
        const int r = ch >> 3, col = ch & 7;
        const size_t go = (size_t)(u0 + r) * D_SZ + kc + col * 8;
        CP16(sbase + OFF_BHI + r * APITCH + col * 16, g_W2t_hi + go);
        CP16(sbase + OFF_BLO + r * APITCH + col * 16, g_W2t_lo + go);
    }
}

__global__ __launch_bounds__(512, 1) void score_mma_kernel(
    const float* __restrict__ Wv, const float* __restrict__ bvp) {
    extern __shared__ char sm[];
    const uint32_t base = smem_u32(sm);
    float2* sAWv = (float2*)(sm + EX);
    float(*sred)[TT] = (float(*)[TT])(sm + EX + 1024);

    const int tid = threadIdx.x;
    const int wid = tid >> 5;
    const int lane = tid & 31;
    const int b = blockIdx.y;
    const int t0 = blockIdx.x * TT;

    const int m0 = (wid & 7) * 32;
    const int wn = wid >> 3;
    const int n0 = wn * 64;

    const __half* Abase = g_vh + ((size_t)b * T_SZ + t0) * D_SZ;

    // ldmatrix per-lane relative offsets
    const int mat = lane >> 3, mr = lane & 7;
    uint32_t aoff[2], boff[4];
#pragma unroll
    for (int mt = 0; mt < 2; mt++)
        aoff[mt] = (m0 + mt * 16 + (mat & 1) * 8 + mr) * APITCH + (mat >> 1) * 16;
#pragma unroll
    for (int ntp = 0; ntp < 4; ntp++)
        boff[ntp] = OFF_BHI + (n0 + ntp * 16 + (mat >> 1) * 8 + mr) * APITCH
                    + (mat & 1) * 16;

    const int fr = lane >> 2;
    const int fc = (lane & 3) * 2;
    const float INV32 = 0.03125f;

    float s_part[4] = {0.f, 0.f, 0.f, 0.f};

    for (int p = 0; p < NPASS; p++) {
        const int u0 = p * UC;
        __syncthreads();   // prev epilogue done with sAWv
        if (tid < UC) sAWv[tid] = make_float2(g_A[b * U_SZ + u0 + tid], Wv[u0 + tid]);

        float acc[2][8][4];
#pragma unroll
        for (int mt = 0; mt < 2; mt++)
#pragma unroll
            for (int nt = 0; nt < 8; nt++)
#pragma unroll
                for (int ci = 0; ci < 4; ci++) acc[mt][nt][ci] = 0.f;

        issue_chunk(base, Abase, u0, 0, tid);
        CP_COMMIT();

#pragma unroll 1
        for (int c = 0; c < NCHUNK; c++) {
            if (c + 1 < NCHUNK) {
                issue_chunk(base + ((c + 1) & 1) * STAGE, Abase, u0, (c + 1) * KC, tid);
                CP_COMMIT();
                CP_WAIT(1);
            } else {
                CP_WAIT(0);
            }
            __syncthreads();

            const uint32_t st = base + (c & 1) * STAGE;
#pragma unroll
            for (int ks = 0; ks < 4; ks++) {
                const uint32_t ko = ks * 32;
                uint32_t ah[2][4];
#pragma unroll
                for (int mt = 0; mt < 2; mt++)
                    LDSM4(ah[mt][0], ah[mt][1], ah[mt][2], ah[mt][3],
                          st + aoff[mt] + ko);
#pragma unroll
                for (int ntp = 0; ntp < 4; ntp++) {
                    uint32_t bh0, bh1, bh2, bh3, bl0, bl1, bl2, bl3;
                    LDSM4(bh0, bh1, bh2, bh3, st + boff[ntp] + ko);
                    LDSM4(bl0, bl1, bl2, bl3,
                          st + boff[ntp] + (OFF_BLO - OFF_BHI) + ko);
#pragma unroll
                    for (int mt = 0; mt < 2; mt++) {
                        MMA_F16(acc[mt][ntp * 2 + 0], ah[mt], bh0, bh1);
                        MMA_F16(acc[mt][ntp * 2 + 1], ah[mt], bh2, bh3);
                        MMA_F16(acc[mt][ntp * 2 + 0], ah[mt], bl0, bl1);
                        MMA_F16(acc[mt][ntp * 2 + 1], ah[mt], bl2, bl3);
                    }
                }
            }
            __syncthreads();   // reads done before next overwrite of this stage
        }

        // epilogue: s += Wv[u] * tanh(D/32 + Aq[u])
#pragma unroll
        for (int mt = 0; mt < 2; mt++)
#pragma unroll
            for (int h2 = 0; h2 < 2; h2++) {
                float a = 0.f;
#pragma unroll
                for (int nt = 0; nt < 8; nt++) {
                    const int cl = n0 + nt * 8 + fc;
                    const float2 aw0 = sAWv[cl];
                    const float2 aw1 = sAWv[cl + 1];
                    a += aw0.y * tanh_approx(fmaf(acc[mt][nt][h2 * 2 + 0], INV32, aw0.x));
                    a += aw1.y * tanh_approx(fmaf(acc[mt][nt][h2 * 2 + 1], INV32, aw1.x));
                }
                s_part[mt * 2 + h2] += a;
            }
    }

    // reduce quads (lanes sharing a row), then across the 2 n-warps
#pragma unroll
    for (int sp = 0; sp < 4; sp++) {
        float v = s_part[sp];
        v += __shfl_xor_sync(0xffffffffu, v, 1);
        v += __shfl_xor_sync(0xffffffffu, v, 2);
        if ((lane & 3) == 0) sred[wn][m0 + sp * 8 + fr] = v;
    }
    __syncthreads();
    if (tid < TT)
        g_score[b * T_SZ + t0 + tid] = sred[0][tid] + sred[1][tid] + bvp[0];
}

// ---------------------------------------------------------------------------
// Kernel 3: softmax over T per batch -> attention weights
// ---------------------------------------------------------------------------
__global__ __launch_bounds__(256) void softmax_kernel(float* __restrict__ wout) {
    __shared__ float red[256];
    const int b = blockIdx.x;
    const int tid = threadIdx.x;
    const float* s = g_score + b * T_SZ;
    float* w = wout + b * T_SZ;

    float m = -3.4e38f;
    for (int t = tid; t < T_SZ; t += 256) m = fmaxf(m, s[t]);
    red[tid] = m;
    __syncthreads();
    for (int o = 128; o > 0; o >>= 1) {
        if (tid < o) red[tid] = fmaxf(red[tid], red[tid + o]);
        __syncthreads();
    }
    const float mx = red[0];
    __syncthreads();

    float sum = 0.f;
    for (int t = tid; t < T_SZ; t += 256) {
        float e = __expf(s[t] - mx);
        w[t] = e;
        sum += e;
    }
    red[tid] = sum;
    __syncthreads();
    for (int o = 128; o > 0; o >>= 1) {
        if (tid < o) red[tid] += red[tid + o];
        __syncthreads();
    }
    const float inv = 1.0f / red[0];
    for (int t = tid; t < T_SZ; t += 256) w[t] *= inv;
}

// ---------------------------------------------------------------------------
// Kernel 4/5: context = sum_t w*values  (t split 4-way, deterministic reduce)
// ---------------------------------------------------------------------------
__global__ __launch_bounds__(256) void context_part_kernel(
    const float* __restrict__ values, const float* __restrict__ w) {
    __shared__ float wsh[512];
    const int b = blockIdx.y;
    const int z = blockIdx.z;
    const int d = blockIdx.x * 256 + threadIdx.x;
    const int t0 = z * 512;
    for (int i = threadIdx.x; i < 512; i += 256) wsh[i] = w[b * T_SZ + t0 + i];
    __syncthreads();
    const float* vb = values + ((size_t)b * T_SZ + t0) * D_SZ + d;
    float a0 = 0.f, a1 = 0.f, a2 = 0.f, a3 = 0.f;
#pragma unroll 4
    for (int t = 0; t < 512; t += 4) {
        a0 += wsh[t + 0] * vb[(size_t)(t + 0) * D_SZ];
        a1 += wsh[t + 1] * vb[(size_t)(t + 1) * D_SZ];
        a2 += wsh[t + 2] * vb[(size_t)(t + 2) * D_SZ];
        a3 += wsh[t + 3] * vb[(size_t)(t + 3) * D_SZ];
    }
    g_cpart[((size_t)z * B_SZ + b) * D_SZ + d] = (a0 + a1) + (a2 + a3);
}

__global__ void context_reduce_kernel(float* __restrict__ out) {
    const int b = blockIdx.x;
    const int d = threadIdx.x;
    float s = 0.f;
#pragma unroll
    for (int z = 0; z < 4; z++) s += g_cpart[((size_t)z * B_SZ + b) * D_SZ + d];
    out[b * D_SZ + d] = s;
}

// ---------------------------------------------------------------------------
extern "C" void kernel_launch(void* const* d_in, const int* in_sizes, int n_in,
                              void* d_out, int out_size) {
    const float* query  = (const float*)d_in[0];
    const float* values = (const float*)d_in[1];
    const float* W1     = (const float*)d_in[2];
    const float* b1     = (const float*)d_in[3];
    const float* W2     = (const float*)d_in[4];
    const float* b2     = (const float*)d_in[5];
    const float* Wv     = (const float*)d_in[6];
    const float* bv     = (const float*)d_in[7];

    float* out = (float*)d_out;
    float* ctx_out = out;                  // [B, D]
    float* w_out   = out + B_SZ * D_SZ;    // [B, T, 1]

    static int smem_set = 0;
    if (!smem_set) {
        cudaFuncSetAttribute(score_mma_kernel,
                             cudaFuncAttributeMaxDynamicSharedMemorySize, SMEM_BYTES);
        smem_set = 1;
    }

    // launch index 3 = score_mma_kernel (ncu captures index 3 in this harness)
    vprep_kernel<<<32768, 256>>>(values);                            // 0
    w2t_prep_kernel<<<dim3(D_SZ / 32, U_SZ / 32), 256>>>(W2);        // 1
    qproj_kernel<<<dim3(4, B_SZ), 256>>>(query, W1, b1, b2);         // 2
    score_mma_kernel<<<dim3(T_SZ / TT, B_SZ), 512, SMEM_BYTES>>>(Wv, bv);  // 3
    softmax_kernel<<<B_SZ, 256>>>(w_out);                            // 4
    context_part_kernel<<<dim3(4, B_SZ, 4), 256>>>(values, w_out);   // 5
    context_reduce_kernel<<<B_SZ, 1024>>>(ctx_out);                  // 6
}

// round 5
// speedup vs baseline: 6.6877x; 1.7356x over previous
#include <cuda_runtime.h>
#include <cuda_fp16.h>
#include <cstdint>
#include <math.h>

#define B_SZ 32
#define T_SZ 2048
#define D_SZ 1024
#define U_SZ 1024

typedef unsigned long long u64;

// ---------------- static device scratch (no runtime allocation) -------------
__device__ float g_A[B_SZ * U_SZ];               // q@W1 + b1 + b2
__device__ float g_score[B_SZ * T_SZ];           // raw scores
__device__ float g_cpart[4 * B_SZ * D_SZ];       // context partials
__device__ __half g_W2t[U_SZ * D_SZ];            // W2^T fp16 [u][d]
__device__ __half g_vh[67108864];                // values as fp16 (B*T*D)

// ---------------- PTX helpers ----------------------------------------------
__device__ __forceinline__ uint32_t smem_u32(const void* p) {
    uint32_t a;
    asm("{ .reg .u64 t; cvta.to.shared.u64 t, %1; cvt.u32.u64 %0, t; }"
        : "=r"(a) : "l"(p));
    return a;
}
__device__ __forceinline__ float tanh_approx(float x) {
    float y;
    asm("tanh.approx.f32 %0, %1;" : "=f"(y) : "f"(x));
    return y;
}
#define CP16(s, g) \
    asm volatile("cp.async.cg.shared.global [%0], [%1], 16;" :: "r"(s), "l"(g))
#define CP_COMMIT() asm volatile("cp.async.commit_group;" ::: "memory")
#define CP_WAIT(n) asm volatile("cp.async.wait_group %0;" :: "n"(n) : "memory")
#define LDSM4(R0, R1, R2, R3, A) \
    asm volatile("ldmatrix.sync.aligned.m8n8.x4.shared.b16 {%0,%1,%2,%3}, [%4];" \
                 : "=r"(R0), "=r"(R1), "=r"(R2), "=r"(R3) : "r"(A))
#define MMA_F16(d, a, b0, b1)                                               \
    asm volatile(                                                           \
        "mma.sync.aligned.m16n8k16.row.col.f32.f16.f16.f32 "                \
        "{%0,%1,%2,%3}, {%4,%5,%6,%7}, {%8,%9}, {%0,%1,%2,%3};"             \
        : "+f"((d)[0]), "+f"((d)[1]), "+f"((d)[2]), "+f"((d)[3])            \
        : "r"((a)[0]), "r"((a)[1]), "r"((a)[2]), "r"((a)[3]),               \
          "r"(b0), "r"(b1))

// ---------------------------------------------------------------------------
// Kernel P0: values fp32 -> fp16 (one uint4 = 8 halves per thread)
// ---------------------------------------------------------------------------
__global__ __launch_bounds__(256) void vprep_kernel(const float* __restrict__ v) {
    const size_t i8 = (size_t)blockIdx.x * 256 + threadIdx.x;
    const float4 v0 = ((const float4*)v)[i8 * 2];
    const float4 v1 = ((const float4*)v)[i8 * 2 + 1];
    uint4 o;
    __half2 h;
    h = __floats2half2_rn(v0.x, v0.y); o.x = *(unsigned*)&h;
    h = __floats2half2_rn(v0.z, v0.w); o.y = *(unsigned*)&h;
    h = __floats2half2_rn(v1.x, v1.y); o.z = *(unsigned*)&h;
    h = __floats2half2_rn(v1.z, v1.w); o.w = *(unsigned*)&h;
    ((uint4*)g_vh)[i8] = o;
}

// ---------------------------------------------------------------------------
// Kernel P1: W2 -> transposed fp16 (tiled transpose)
// ---------------------------------------------------------------------------
__global__ __launch_bounds__(256) void w2t_prep_kernel(const float* __restrict__ W2) {
    __shared__ float tile[32][33];
    const int d0 = blockIdx.x * 32, u0 = blockIdx.y * 32;
    const int tx = threadIdx.x & 31, ty = threadIdx.x >> 5;   // 32 x 8
#pragma unroll
    for (int i = 0; i < 4; i++)
        tile[ty * 4 + i][tx] = W2[(size_t)(d0 + ty * 4 + i) * U_SZ + u0 + tx];
    __syncthreads();
#pragma unroll
    for (int i = 0; i < 4; i++) {
        const int u = u0 + ty * 4 + i;
        g_W2t[(size_t)u * D_SZ + d0 + tx] = __float2half_rn(tile[tx][ty * 4 + i]);
    }
}

// ---------------------------------------------------------------------------
// Kernel 1: A[b,u] = q@W1 + b1 + b2   (fp32, exact)
// ---------------------------------------------------------------------------
__global__ __launch_bounds__(256) void qproj_kernel(
    const float* __restrict__ query, const float* __restrict__ W1,
    const float* __restrict__ b1, const float* __restrict__ b2) {
    __shared__ float qs[D_SZ];
    const int b = blockIdx.y;
    const int u = blockIdx.x * 256 + threadIdx.x;
#pragma unroll
    for (int i = 0; i < 4; i++)
        qs[threadIdx.x + i * 256] = query[b * D_SZ + threadIdx.x + i * 256];
    __syncthreads();
    float a0 = 0.f, a1 = 0.f, a2 = 0.f, a3 = 0.f;
#pragma unroll 4
    for (int d = 0; d < D_SZ; d += 4) {
        a0 += qs[d + 0] * W1[(size_t)(d + 0) * U_SZ + u];
        a1 += qs[d + 1] * W1[(size_t)(d + 1) * U_SZ + u];
        a2 += qs[d + 2] * W1[(size_t)(d + 2) * U_SZ + u];
        a3 += qs[d + 3] * W1[(size_t)(d + 3) * U_SZ + u];
    }
    g_A[b * U_SZ + u] = b1[u] + b2[u] + ((a0 + a1) + (a2 + a3));
}

// ---------------------------------------------------------------------------
// Kernel 2 (dominant): single-fp16 mma.sync GEMM + tanh + Wv reduce -> scores
// CTA: one b, 128 t-rows; 256 threads = 8 warps (4m x 2n), warp tile 32x64.
// Flattened (pass, chunk) pipeline: 8 u-passes x 16 K-chunks of 64,
// 3-stage cp.async smem pipeline, one __syncthreads per chunk, 2 CTAs/SM.
// ---------------------------------------------------------------------------
#define TT 128
#define UC 128
#define KC 64
#define OFF_B 16384
#define STAGE 32768
#define NSTG 3
#define EX (NSTG * STAGE)                 // 98304
#define SMEM_BYTES (EX + 2048 + 1024)     // + sAWv[2][128] + sred[2][128]

__device__ __forceinline__ void issue_chunk(
    uint32_t sbase, const __half* Abase, int u0, int kc, int tid) {
#pragma unroll
    for (int i = 0; i < 4; i++) {
        const int idx = i * 256 + tid;
        const int r = idx >> 3;
        const int c8 = idx & 7;
        const uint32_t sw = (uint32_t)(c8 * 16) ^ (((uint32_t)r & 7u) << 4);
        CP16(sbase + r * 128 + sw, Abase + (size_t)r * D_SZ + kc + c8 * 8);
        CP16(sbase + OFF_B + r * 128 + sw,
             g_W2t + (size_t)(u0 + r) * D_SZ + kc + c8 * 8);
    }
}

__global__ __launch_bounds__(256, 2) void score_mma_kernel(
    const float* __restrict__ Wv, const float* __restrict__ bvp) {
    extern __shared__ char sm[];
    const uint32_t base = smem_u32(sm);
    float2(*sAWv)[UC] = (float2(*)[UC])(sm + EX);
    float(*sred)[TT] = (float(*)[TT])(sm + EX + 2048);

    const int tid = threadIdx.x;
    const int wid = tid >> 5;
    const int lane = tid & 31;
    const int b = blockIdx.y;
    const int t0 = blockIdx.x * TT;

    const int m0 = (wid & 3) * 32;
    const int wn = wid >> 2;
    const int n0 = wn * 64;

    const __half* Abase = g_vh + ((size_t)b * T_SZ + t0) * D_SZ;

    // ldmatrix per-lane address components (mapping verified in R4)
    const int mat = lane >> 3, mr = lane & 7;
    const int rowA = m0 + (mat & 1) * 8 + mr;
    const uint32_t aBase0 = rowA * 128, aBase1 = aBase0 + 16 * 128;
    const uint32_t aXor = ((uint32_t)rowA & 7u) << 4;
    const uint32_t aCb = (mat >> 1) * 16;
    const int rowB0 = n0 + (mat >> 1) * 8 + mr;
    const uint32_t bXor = ((uint32_t)rowB0 & 7u) << 4;
    const uint32_t bCb = (mat & 1) * 16;
    uint32_t bBase[4];
#pragma unroll
    for (int ntp = 0; ntp < 4; ntp++)
        bBase[ntp] = OFF_B + (rowB0 + ntp * 16) * 128;

    const int fr = lane >> 2;
    const int fc = (lane & 3) * 2;

    float s_part[4] = {0.f, 0.f, 0.f, 0.f};
    float acc[2][8][4];

    // prologue: chunks 0, 1
    issue_chunk(base, Abase, 0, 0, tid);
    CP_COMMIT();
    issue_chunk(base + STAGE, Abase, 0, KC, tid);
    CP_COMMIT();

#pragma unroll 1
    for (int gc = 0; gc < 128; gc++) {
        const int c = gc & 15;
        const int p = gc >> 4;

        if (gc < 127) { CP_WAIT(1); } else { CP_WAIT(0); }
        __syncthreads();

        if (gc + 2 < 128) {
            const int g2 = gc + 2;
            issue_chunk(base + (g2 % 3) * STAGE, Abase, (g2 >> 4) * UC,
                        (g2 & 15) * KC, tid);
            CP_COMMIT();
        }

        if (c == 0) {
#pragma unroll
            for (int mt = 0; mt < 2; mt++)
#pragma unroll
                for (int nt = 0; nt < 8; nt++)
#pragma unroll
                    for (int ci = 0; ci < 4; ci++) acc[mt][nt][ci] = 0.f;
            if (tid < UC)
                sAWv[p & 1][tid] =
                    make_float2(g_A[b * U_SZ + p * UC + tid], Wv[p * UC + tid]);
        }

        // ---- compute chunk gc from stage gc%3
        const uint32_t st = base + (gc % 3) * STAGE;
#pragma unroll
        for (int ks = 0; ks < 4; ks++) {
            uint32_t ah[2][4];
            const uint32_t ac = ((uint32_t)(ks * 32) + aCb) ^ aXor;
            LDSM4(ah[0][0], ah[0][1], ah[0][2], ah[0][3], st + aBase0 + ac);
            LDSM4(ah[1][0], ah[1][1], ah[1][2], ah[1][3], st + aBase1 + ac);
            const uint32_t bc = ((uint32_t)(ks * 32) + bCb) ^ bXor;
#pragma unroll
            for (int ntp = 0; ntp < 4; ntp++) {
                uint32_t b0, b1, b2, b3;
                LDSM4(b0, b1, b2, b3, st + bBase[ntp] + bc);
                MMA_F16(acc[0][ntp * 2 + 0], ah[0], b0, b1);
                MMA_F16(acc[0][ntp * 2 + 1], ah[0], b2, b3);
                MMA_F16(acc[1][ntp * 2 + 0], ah[1], b0, b1);
                MMA_F16(acc[1][ntp * 2 + 1], ah[1], b2, b3);
            }
        }

        if (c == 15) {
            // epilogue: s += Wv[u] * tanh(D + Aq[u])
            const float2* aw = sAWv[p & 1];
#pragma unroll
            for (int mt = 0; mt < 2; mt++)
#pragma unroll
                for (int h2 = 0; h2 < 2; h2++) {
                    float a = 0.f;
#pragma unroll
                    for (int nt = 0; nt < 8; nt++) {
                        const int cl = n0 + nt * 8 + fc;
                        const float2 aw0 = aw[cl];
                        const float2 aw1 = aw[cl + 1];
                        a += aw0.y * tanh_approx(acc[mt][nt][h2 * 2 + 0] + aw0.x);
                        a += aw1.y * tanh_approx(acc[mt][nt][h2 * 2 + 1] + aw1.x);
                    }
                    s_part[mt * 2 + h2] += a;
                }
        }
    }

    // ---- reduce quads (lanes sharing a row), then across the 2 n-warps
#pragma unroll
    for (int sp = 0; sp < 4; sp++) {
        float v = s_part[sp];
        v += __shfl_xor_sync(0xffffffffu, v, 1);
        v += __shfl_xor_sync(0xffffffffu, v, 2);
        if ((lane & 3) == 0) sred[wn][m0 + sp * 8 + fr] = v;
    }
    __syncthreads();
    if (tid < TT)
        g_score[b * T_SZ + t0 + tid] = sred[0][tid] + sred[1][tid] + bvp[0];
}

// ---------------------------------------------------------------------------
// Kernel 3: softmax over T per batch -> attention weights
// ---------------------------------------------------------------------------
__global__ __launch_bounds__(256) void softmax_kernel(float* __restrict__ wout) {
    __shared__ float red[256];
    const int b = blockIdx.x;
    const int tid = threadIdx.x;
    const float* s = g_score + b * T_SZ;
    float* w = wout + b * T_SZ;

    float m = -3.4e38f;
    for (int t = tid; t < T_SZ; t += 256) m = fmaxf(m, s[t]);
    red[tid] = m;
    __syncthreads();
    for (int o = 128; o > 0; o >>= 1) {
        if (tid < o) red[tid] = fmaxf(red[tid], red[tid + o]);
        __syncthreads();
    }
    const float mx = red[0];
    __syncthreads();

    float sum = 0.f;
    for (int t = tid; t < T_SZ; t += 256) {
        float e = __expf(s[t] - mx);
        w[t] = e;
        sum += e;
    }
    red[tid] = sum;
    __syncthreads();
    for (int o = 128; o > 0; o >>= 1) {
        if (tid < o) red[tid] += red[tid + o];
        __syncthreads();
    }
    const float inv = 1.0f / red[0];
    for (int t = tid; t < T_SZ; t += 256) w[t] *= inv;
}

// ---------------------------------------------------------------------------
// Kernel 4/5: context = sum_t w*values  (t split 4-way, deterministic reduce)
// ---------------------------------------------------------------------------
__global__ __launch_bounds__(256) void context_part_kernel(
    const float* __restrict__ values, const float* __restrict__ w) {
    __shared__ float wsh[512];
    const int b = blockIdx.y;
    const int z = blockIdx.z;
    const int d = blockIdx.x * 256 + threadIdx.x;
    const int t0 = z * 512;
    for (int i = threadIdx.x; i < 512; i += 256) wsh[i] = w[b * T_SZ + t0 + i];
    __syncthreads();
    const float* vb = values + ((size_t)b * T_SZ + t0) * D_SZ + d;
    float a0 = 0.f, a1 = 0.f, a2 = 0.f, a3 = 0.f;
#pragma unroll 4
    for (int t = 0; t < 512; t += 4) {
        a0 += wsh[t + 0] * vb[(size_t)(t + 0) * D_SZ];
        a1 += wsh[t + 1] * vb[(size_t)(t + 1) * D_SZ];
        a2 += wsh[t + 2] * vb[(size_t)(t + 2) * D_SZ];
        a3 += wsh[t + 3] * vb[(size_t)(t + 3) * D_SZ];
    }
    g_cpart[((size_t)z * B_SZ + b) * D_SZ + d] = (a0 + a1) + (a2 + a3);
}

__global__ void context_reduce_kernel(float* __restrict__ out) {
    const int b = blockIdx.x;
    const int d = threadIdx.x;
    float s = 0.f;
#pragma unroll
    for (int z = 0; z < 4; z++) s += g_cpart[((size_t)z * B_SZ + b) * D_SZ + d];
    out[b * D_SZ + d] = s;
}

// ---------------------------------------------------------------------------
extern "C" void kernel_launch(void* const* d_in, const int* in_sizes, int n_in,
                              void* d_out, int out_size) {
    const float* query  = (const float*)d_in[0];
    const float* values = (const float*)d_in[1];
    const float* W1     = (const float*)d_in[2];
    const float* b1     = (const float*)d_in[3];
    const float* W2     = (const float*)d_in[4];
    const float* b2     = (const float*)d_in[5];
    const float* Wv     = (const float*)d_in[6];
    const float* bv     = (const float*)d_in[7];

    float* out = (float*)d_out;
    float* ctx_out = out;                  // [B, D]
    float* w_out   = out + B_SZ * D_SZ;    // [B, T, 1]

    static int smem_set = 0;
    if (!smem_set) {
        cudaFuncSetAttribute(score_mma_kernel,
                             cudaFuncAttributeMaxDynamicSharedMemorySize, SMEM_BYTES);
        smem_set = 1;
    }

    // launch index 3 = score_mma_kernel (ncu captures index 3 in this harness)
    vprep_kernel<<<32768, 256>>>(values);                            // 0
    w2t_prep_kernel<<<dim3(D_SZ / 32, U_SZ / 32), 256>>>(W2);        // 1
    qproj_kernel<<<dim3(4, B_SZ), 256>>>(query, W1, b1, b2);         // 2
    score_mma_kernel<<<dim3(T_SZ / TT, B_SZ), 256, SMEM_BYTES>>>(Wv, bv);  // 3
    softmax_kernel<<<B_SZ, 256>>>(w_out);                            // 4
    context_part_kernel<<<dim3(4, B_SZ, 4), 256>>>(values, w_out);   // 5
    context_reduce_kernel<<<B_SZ, 1024>>>(ctx_out);                  // 6
}

// round 8
// speedup vs baseline: 7.7923x; 1.1652x over previous
#include <cuda_runtime.h>
#include <cuda_fp16.h>
#include <cstdint>
#include <math.h>

#define B_SZ 32
#define T_SZ 2048
#define D_SZ 1024
#define U_SZ 1024
#define NPASS 8

typedef unsigned long long u64;

// ---------------- static device scratch (no runtime allocation) -------------
__device__ float g_A[B_SZ * U_SZ];               // q@W1 + b1 + b2
__device__ float g_spart[NPASS * B_SZ * T_SZ];   // per-pass partial scores
__device__ float g_cpart[4 * B_SZ * D_SZ];       // context partials
__device__ __half g_W2t[U_SZ * D_SZ];            // W2^T fp16 [u][d]
__device__ __half g_vh[67108864];                // values as fp16 (B*T*D)

// ---------------- PTX helpers ----------------------------------------------
__device__ __forceinline__ uint32_t smem_u32(const void* p) {
    uint32_t a;
    asm("{ .reg .u64 t; cvta.to.shared.u64 t, %1; cvt.u32.u64 %0, t; }"
        : "=r"(a) : "l"(p));
    return a;
}
__device__ __forceinline__ float tanh_approx(float x) {
    float y;
    asm("tanh.approx.f32 %0, %1;" : "=f"(y) : "f"(x));
    return y;
}
#define CP16(s, g) \
    asm volatile("cp.async.cg.shared.global [%0], [%1], 16;" :: "r"(s), "l"(g))
#define CP_COMMIT() asm volatile("cp.async.commit_group;" ::: "memory")
#define CP_WAIT(n) asm volatile("cp.async.wait_group %0;" :: "n"(n) : "memory")
#define LDSM4(R0, R1, R2, R3, A) \
    asm volatile("ldmatrix.sync.aligned.m8n8.x4.shared.b16 {%0,%1,%2,%3}, [%4];" \
                 : "=r"(R0), "=r"(R1), "=r"(R2), "=r"(R3) : "r"(A))
#define MMA_F16(d, a, b0, b1)                                               \
    asm volatile(                                                           \
        "mma.sync.aligned.m16n8k16.row.col.f32.f16.f16.f32 "                \
        "{%0,%1,%2,%3}, {%4,%5,%6,%7}, {%8,%9}, {%0,%1,%2,%3};"             \
        : "+f"((d)[0]), "+f"((d)[1]), "+f"((d)[2]), "+f"((d)[3])            \
        : "r"((a)[0]), "r"((a)[1]), "r"((a)[2]), "r"((a)[3]),               \
          "r"(b0), "r"(b1))

// ---------------------------------------------------------------------------
// Kernel P0: values fp32 -> fp16 (one uint4 = 8 halves per thread)
// ---------------------------------------------------------------------------
__global__ __launch_bounds__(256) void vprep_kernel(const float* __restrict__ v) {
    const size_t i8 = (size_t)blockIdx.x * 256 + threadIdx.x;
    const float4 v0 = ((const float4*)v)[i8 * 2];
    const float4 v1 = ((const float4*)v)[i8 * 2 + 1];
    uint4 o;
    __half2 h;
    h = __floats2half2_rn(v0.x, v0.y); o.x = *(unsigned*)&h;
    h = __floats2half2_rn(v0.z, v0.w); o.y = *(unsigned*)&h;
    h = __floats2half2_rn(v1.x, v1.y); o.z = *(unsigned*)&h;
    h = __floats2half2_rn(v1.z, v1.w); o.w = *(unsigned*)&h;
    ((uint4*)g_vh)[i8] = o;
}

// ---------------------------------------------------------------------------
// Kernel P1: W2 -> transposed fp16 (tiled transpose)
// ---------------------------------------------------------------------------
__global__ __launch_bounds__(256) void w2t_prep_kernel(const float* __restrict__ W2) {
    __shared__ float tile[32][33];
    const int d0 = blockIdx.x * 32, u0 = blockIdx.y * 32;
    const int tx = threadIdx.x & 31, ty = threadIdx.x >> 5;   // 32 x 8
#pragma unroll
    for (int i = 0; i < 4; i++)
        tile[ty * 4 + i][tx] = W2[(size_t)(d0 + ty * 4 + i) * U_SZ + u0 + tx];
    __syncthreads();
#pragma unroll
    for (int i = 0; i < 4; i++) {
        const int u = u0 + ty * 4 + i;
        g_W2t[(size_t)u * D_SZ + d0 + tx] = __float2half_rn(tile[tx][ty * 4 + i]);
    }
}

// ---------------------------------------------------------------------------
// Kernel 1: A[b,u] = q@W1 + b1 + b2   (fp32, exact)
// ---------------------------------------------------------------------------
__global__ __launch_bounds__(256) void qproj_kernel(
    const float* __restrict__ query, const float* __restrict__ W1,
    const float* __restrict__ b1, const float* __restrict__ b2) {
    __shared__ float qs[D_SZ];
    const int b = blockIdx.y;
    const int u = blockIdx.x * 256 + threadIdx.x;
#pragma unroll
    for (int i = 0; i < 4; i++)
        qs[threadIdx.x + i * 256] = query[b * D_SZ + threadIdx.x + i * 256];
    __syncthreads();
    float a0 = 0.f, a1 = 0.f, a2 = 0.f, a3 = 0.f;
#pragma unroll 4
    for (int d = 0; d < D_SZ; d += 4) {
        a0 += qs[d + 0] * W1[(size_t)(d + 0) * U_SZ + u];
        a1 += qs[d + 1] * W1[(size_t)(d + 1) * U_SZ + u];
        a2 += qs[d + 2] * W1[(size_t)(d + 2) * U_SZ + u];
        a3 += qs[d + 3] * W1[(size_t)(d + 3) * U_SZ + u];
    }
    g_A[b * U_SZ + u] = b1[u] + b2[u] + ((a0 + a1) + (a2 + a3));
}

// ---------------------------------------------------------------------------
// Kernel 2 (dominant): fp16 mma.sync GEMM + tanh + Wv partial reduce
// Work unit = one (t-tile, u-pass): grid (16 t, 32 b, 8 pass) = 4096 CTAs.
// CTA: 128 t-rows x 128 u-cols x K=1024; 256 threads = 8 warps (4m x 2n),
// warp tile 32x64. 16 K-chunks of 64, 3-stage cp.async pipeline, 2 CTAs/SM.
// Writes per-pass partial scores (summed deterministically in softmax).
// ---------------------------------------------------------------------------
#define TT 128
#define UC 128
#define KC 64
#define NCHUNK 16
#define OFF_B 16384
#define STAGE 32768
#define EX (3 * STAGE)                    // 98304
#define SMEM_BYTES (EX + 1024 + 1024)     // + sAWv[128] + sred[2][128]

__device__ __forceinline__ void issue_chunk(
    uint32_t sbase, const __half* Abase, const __half* Bbase, int kc, int tid) {
#pragma unroll
    for (int i = 0; i < 4; i++) {
        const int idx = i * 256 + tid;
        const int r = idx >> 3;
        const int c8 = idx & 7;
        const uint32_t sw = (uint32_t)(c8 * 16) ^ (((uint32_t)r & 7u) << 4);
        CP16(sbase + r * 128 + sw, Abase + (size_t)r * D_SZ + kc + c8 * 8);
        CP16(sbase + OFF_B + r * 128 + sw, Bbase + (size_t)r * D_SZ + kc + c8 * 8);
    }
}

__global__ __launch_bounds__(256, 2) void score_mma_kernel(
    const float* __restrict__ Wv) {
    extern __shared__ char sm[];
    const uint32_t base = smem_u32(sm);
    float2* sAWv = (float2*)(sm + EX);
    float(*sred)[TT] = (float(*)[TT])(sm + EX + 1024);

    const int tid = threadIdx.x;
    const int wid = tid >> 5;
    const int lane = tid & 31;
    const int b = blockIdx.y;
    const int t0 = blockIdx.x * TT;
    const int p = blockIdx.z;
    const int u0 = p * UC;

    const int m0 = (wid & 3) * 32;
    const int wn = wid >> 2;
    const int n0 = wn * 64;

    const __half* Abase = g_vh + ((size_t)b * T_SZ + t0) * D_SZ;
    const __half* Bbase = g_W2t + (size_t)u0 * D_SZ;

    if (tid < UC)
        sAWv[tid] = make_float2(g_A[b * U_SZ + u0 + tid], Wv[u0 + tid]);

    // ldmatrix per-lane address components (mapping verified in R4/R5)
    const int mat = lane >> 3, mr = lane & 7;
    const int rowA = m0 + (mat & 1) * 8 + mr;
    const uint32_t aBase0 = rowA * 128, aBase1 = aBase0 + 16 * 128;
    const uint32_t aXor = ((uint32_t)rowA & 7u) << 4;
    const uint32_t aCb = (mat >> 1) * 16;
    const int rowB0 = n0 + (mat >> 1) * 8 + mr;
    const uint32_t bXor = ((uint32_t)rowB0 & 7u) << 4;
    const uint32_t bCb = (mat & 1) * 16;
    uint32_t bBase[4];
#pragma unroll
    for (int ntp = 0; ntp < 4; ntp++)
        bBase[ntp] = OFF_B + (rowB0 + ntp * 16) * 128;

    const int fr = lane >> 2;
    const int fc = (lane & 3) * 2;

    float acc[2][8][4];
#pragma unroll
    for (int mt = 0; mt < 2; mt++)
#pragma unroll
        for (int nt = 0; nt < 8; nt++)
#pragma unroll
            for (int ci = 0; ci < 4; ci++) acc[mt][nt][ci] = 0.f;

    // prologue: chunks 0, 1
    issue_chunk(base, Abase, Bbase, 0, tid);
    CP_COMMIT();
    issue_chunk(base + STAGE, Abase, Bbase, KC, tid);
    CP_COMMIT();

#pragma unroll 1
    for (int c = 0; c < NCHUNK; c++) {
        if (c < NCHUNK - 1) { CP_WAIT(1); } else { CP_WAIT(0); }
        __syncthreads();

        if (c + 2 < NCHUNK) {
            issue_chunk(base + ((c + 2) % 3) * STAGE, Abase, Bbase,
                        (c + 2) * KC, tid);
            CP_COMMIT();
        }

        const uint32_t st = base + (c % 3) * STAGE;
#pragma unroll
        for (int ks = 0; ks < 4; ks++) {
            uint32_t ah[2][4];
            const uint32_t ac = ((uint32_t)(ks * 32) + aCb) ^ aXor;
            LDSM4(ah[0][0], ah[0][1], ah[0][2], ah[0][3], st + aBase0 + ac);
            LDSM4(ah[1][0], ah[1][1], ah[1][2], ah[1][3], st + aBase1 + ac);
            const uint32_t bc = ((uint32_t)(ks * 32) + bCb) ^ bXor;
#pragma unroll
            for (int ntp = 0; ntp < 4; ntp++) {
                uint32_t b0, b1, b2, b3;
                LDSM4(b0, b1, b2, b3, st + bBase[ntp] + bc);
                MMA_F16(acc[0][ntp * 2 + 0], ah[0], b0, b1);
                MMA_F16(acc[0][ntp * 2 + 1], ah[0], b2, b3);
                MMA_F16(acc[1][ntp * 2 + 0], ah[1], b0, b1);
                MMA_F16(acc[1][ntp * 2 + 1], ah[1], b2, b3);
            }
        }
        __syncthreads();   // reads done before this stage is overwritten
    }

    // ---- epilogue: s = sum_u Wv[u] * tanh(D + Aq[u]) over this pass's 128 u
    float s_part[4];
#pragma unroll
    for (int mt = 0; mt < 2; mt++)
#pragma unroll
        for (int h2 = 0; h2 < 2; h2++) {
            float a = 0.f;
#pragma unroll
            for (int nt = 0; nt < 8; nt++) {
                const int cl = n0 + nt * 8 + fc;
                const float2 aw0 = sAWv[cl];
                const float2 aw1 = sAWv[cl + 1];
                a += aw0.y * tanh_approx(acc[mt][nt][h2 * 2 + 0] + aw0.x);
                a += aw1.y * tanh_approx(acc[mt][nt][h2 * 2 + 1] + aw1.x);
            }
            s_part[mt * 2 + h2] = a;
        }

    // reduce quads (lanes sharing a row), then across the 2 n-warps
#pragma unroll
    for (int sp = 0; sp < 4; sp++) {
        float v = s_part[sp];
        v += __shfl_xor_sync(0xffffffffu, v, 1);
        v += __shfl_xor_sync(0xffffffffu, v, 2);
        if ((lane & 3) == 0) sred[wn][m0 + sp * 8 + fr] = v;
    }
    __syncthreads();
    if (tid < TT)
        g_spart[((size_t)p * B_SZ + b) * T_SZ + t0 + tid] =
            sred[0][tid] + sred[1][tid];
}

// ---------------------------------------------------------------------------
// Kernel 3: sum pass-partials + softmax over T per batch -> attention weights
// ---------------------------------------------------------------------------
__global__ __launch_bounds__(256) void softmax_kernel(
    float* __restrict__ wout, const float* __restrict__ bvp) {
    __shared__ float red[256];
    __shared__ float sc[T_SZ];
    const int b = blockIdx.x;
    const int tid = threadIdx.x;
    float* w = wout + b * T_SZ;
    const float bv0 = bvp[0];

    float m = -3.4e38f;
    for (int t = tid; t < T_SZ; t += 256) {
        float s = bv0;
#pragma unroll
        for (int p = 0; p < NPASS; p++)
            s += g_spart[((size_t)p * B_SZ + b) * T_SZ + t];
        sc[t] = s;
        m = fmaxf(m, s);
    }
    red[tid] = m;
    __syncthreads();
    for (int o = 128; o > 0; o >>= 1) {
        if (tid < o) red[tid] = fmaxf(red[tid], red[tid + o]);
        __syncthreads();
    }
    const float mx = red[0];
    __syncthreads();

    float sum = 0.f;
    for (int t = tid; t < T_SZ; t += 256) {
        float e = __expf(sc[t] - mx);
        w[t] = e;
        sum += e;
    }
    red[tid] = sum;
    __syncthreads();
    for (int o = 128; o > 0; o >>= 1) {
        if (tid < o) red[tid] += red[tid + o];
        __syncthreads();
    }
    const float inv = 1.0f / red[0];
    for (int t = tid; t < T_SZ; t += 256) w[t] *= inv;
}

// ---------------------------------------------------------------------------
// Kernel 4/5: context = sum_t w*values (fp16 values, half2 loads, 4-way split)
// ---------------------------------------------------------------------------
__global__ __launch_bounds__(256) void context_part_kernel(
    const float* __restrict__ w) {
    __shared__ float wsh[512];
    const int b = blockIdx.y;
    const int z = blockIdx.z;
    const int d2 = blockIdx.x * 256 + threadIdx.x;   // half2 index (0..511)
    const int t0 = z * 512;
    for (int i = threadIdx.x; i < 512; i += 256) wsh[i] = w[b * T_SZ + t0 + i];
    __syncthreads();
    const __half2* vb = (const __half2*)(g_vh + ((size_t)b * T_SZ + t0) * D_SZ) + d2;
    float2 a0 = {0.f, 0.f}, a1 = {0.f, 0.f};
#pragma unroll 4
    for (int t = 0; t < 512; t += 2) {
        const float2 v0 = __half22float2(vb[(size_t)(t + 0) * (D_SZ / 2)]);
        const float2 v1 = __half22float2(vb[(size_t)(t + 1) * (D_SZ / 2)]);
        const float w0 = wsh[t + 0], w1 = wsh[t + 1];
        a0.x += w0 * v0.x; a0.y += w0 * v0.y;
        a1.x += w1 * v1.x; a1.y += w1 * v1.y;
    }
    float2 r;
    r.x = a0.x + a1.x;
    r.y = a0.y + a1.y;
    ((float2*)(g_cpart + ((size_t)z * B_SZ + b) * D_SZ))[d2] = r;
}

__global__ void context_reduce_kernel(float* __restrict__ out) {
    const int b = blockIdx.x;
    const int d = threadIdx.x;
    float s = 0.f;
#pragma unroll
    for (int z = 0; z < 4; z++) s += g_cpart[((size_t)z * B_SZ + b) * D_SZ + d];
    out[b * D_SZ + d] = s;
}

// ---------------------------------------------------------------------------
extern "C" void kernel_launch(void* const* d_in, const int* in_sizes, int n_in,
                              void* d_out, int out_size) {
    const float* query  = (const float*)d_in[0];
    const float* values = (const float*)d_in[1];
    const float* W1     = (const float*)d_in[2];
    const float* b1     = (const float*)d_in[3];
    const float* W2     = (const float*)d_in[4];
    const float* b2     = (const float*)d_in[5];
    const float* Wv     = (const float*)d_in[6];
    const float* bv     = (const float*)d_in[7];

    float* out = (float*)d_out;
    float* ctx_out = out;                  // [B, D]
    float* w_out   = out + B_SZ * D_SZ;    // [B, T, 1]

    static int smem_set = 0;
    if (!smem_set) {
        cudaFuncSetAttribute(score_mma_kernel,
                             cudaFuncAttributeMaxDynamicSharedMemorySize, SMEM_BYTES);
        smem_set = 1;
    }

    // launch index 3 = score_mma_kernel (ncu captures index 3 in this harness)
    vprep_kernel<<<32768, 256>>>(values);                            // 0
    w2t_prep_kernel<<<dim3(D_SZ / 32, U_SZ / 32), 256>>>(W2);        // 1
    qproj_kernel<<<dim3(4, B_SZ), 256>>>(query, W1, b1, b2);         // 2
    score_mma_kernel<<<dim3(T_SZ / TT, B_SZ, NPASS), 256, SMEM_BYTES>>>(Wv); // 3
    softmax_kernel<<<B_SZ, 256>>>(w_out, bv);                        // 4
    context_part_kernel<<<dim3(2, B_SZ, 4), 256>>>(w_out);           // 5
    context_reduce_kernel<<<B_SZ, 1024>>>(ctx_out);                  // 6
}

// round 10
// speedup vs baseline: 8.0857x; 1.0376x over previous
#include <cuda_runtime.h>
#include <cuda_fp16.h>
#include <cstdint>
#include <math.h>

#define B_SZ 32
#define T_SZ 2048
#define D_SZ 1024
#define U_SZ 1024
#define NPASS 8
#define CSPLIT 8

typedef unsigned long long u64;

// ---------------- static device scratch (no runtime allocation) -------------
__device__ float g_A[B_SZ * U_SZ];               // q@W1 + b1 + b2
__device__ float g_spart[NPASS * B_SZ * T_SZ];   // per-pass partial scores
__device__ float g_cpart[CSPLIT * B_SZ * D_SZ];  // context partials
__device__ __half g_W2t[U_SZ * D_SZ];            // W2^T fp16 [u][d]
__device__ __half g_vh[67108864];                // values as fp16 (B*T*D)

// ---------------- PTX helpers ----------------------------------------------
__device__ __forceinline__ uint32_t smem_u32(const void* p) {
    uint32_t a;
    asm("{ .reg .u64 t; cvta.to.shared.u64 t, %1; cvt.u32.u64 %0, t; }"
        : "=r"(a) : "l"(p));
    return a;
}
__device__ __forceinline__ float tanh_approx(float x) {
    float y;
    asm("tanh.approx.f32 %0, %1;" : "=f"(y) : "f"(x));
    return y;
}
#define CP16(s, g) \
    asm volatile("cp.async.cg.shared.global [%0], [%1], 16;" :: "r"(s), "l"(g))
#define CP_COMMIT() asm volatile("cp.async.commit_group;" ::: "memory")
#define CP_WAIT(n) asm volatile("cp.async.wait_group %0;" :: "n"(n) : "memory")
#define LDSM4(R0, R1, R2, R3, A) \
    asm volatile("ldmatrix.sync.aligned.m8n8.x4.shared.b16 {%0,%1,%2,%3}, [%4];" \
                 : "=r"(R0), "=r"(R1), "=r"(R2), "=r"(R3) : "r"(A))
#define MMA_F16(d, a, b0, b1)                                               \
    asm volatile(                                                           \
        "mma.sync.aligned.m16n8k16.row.col.f32.f16.f16.f32 "                \
        "{%0,%1,%2,%3}, {%4,%5,%6,%7}, {%8,%9}, {%0,%1,%2,%3};"             \
        : "+f"((d)[0]), "+f"((d)[1]), "+f"((d)[2]), "+f"((d)[3])            \
        : "r"((a)[0]), "r"((a)[1]), "r"((a)[2]), "r"((a)[3]),               \
          "r"(b0), "r"(b1))

// ---------------------------------------------------------------------------
// Kernel P0: values fp32 -> fp16 (one uint4 = 8 halves per thread)
// ---------------------------------------------------------------------------
__global__ __launch_bounds__(256) void vprep_kernel(const float* __restrict__ v) {
    const size_t i8 = (size_t)blockIdx.x * 256 + threadIdx.x;
    const float4 v0 = ((const float4*)v)[i8 * 2];
    const float4 v1 = ((const float4*)v)[i8 * 2 + 1];
    uint4 o;
    __half2 h;
    h = __floats2half2_rn(v0.x, v0.y); o.x = *(unsigned*)&h;
    h = __floats2half2_rn(v0.z, v0.w); o.y = *(unsigned*)&h;
    h = __floats2half2_rn(v1.x, v1.y); o.z = *(unsigned*)&h;
    h = __floats2half2_rn(v1.z, v1.w); o.w = *(unsigned*)&h;
    ((uint4*)g_vh)[i8] = o;
}

// ---------------------------------------------------------------------------
// Kernel P1: W2 -> transposed fp16 (tiled transpose)
// ---------------------------------------------------------------------------
__global__ __launch_bounds__(256) void w2t_prep_kernel(const float* __restrict__ W2) {
    __shared__ float tile[32][33];
    const int d0 = blockIdx.x * 32, u0 = blockIdx.y * 32;
    const int tx = threadIdx.x & 31, ty = threadIdx.x >> 5;   // 32 x 8
#pragma unroll
    for (int i = 0; i < 4; i++)
        tile[ty * 4 + i][tx] = W2[(size_t)(d0 + ty * 4 + i) * U_SZ + u0 + tx];
    __syncthreads();
#pragma unroll
    for (int i = 0; i < 4; i++) {
        const int u = u0 + ty * 4 + i;
        g_W2t[(size_t)u * D_SZ + d0 + tx] = __float2half_rn(tile[tx][ty * 4 + i]);
    }
}

// ---------------------------------------------------------------------------
// Kernel 1: A[b,u] = q@W1 + b1 + b2   (fp32, exact)
// ---------------------------------------------------------------------------
__global__ __launch_bounds__(256) void qproj_kernel(
    const float* __restrict__ query, const float* __restrict__ W1,
    const float* __restrict__ b1, const float* __restrict__ b2) {
    __shared__ float qs[D_SZ];
    const int b = blockIdx.y;
    const int u = blockIdx.x * 256 + threadIdx.x;
#pragma unroll
    for (int i = 0; i < 4; i++)
        qs[threadIdx.x + i * 256] = query[b * D_SZ + threadIdx.x + i * 256];
    __syncthreads();
    float a0 = 0.f, a1 = 0.f, a2 = 0.f, a3 = 0.f;
#pragma unroll 4
    for (int d = 0; d < D_SZ; d += 4) {
        a0 += qs[d + 0] * W1[(size_t)(d + 0) * U_SZ + u];
        a1 += qs[d + 1] * W1[(size_t)(d + 1) * U_SZ + u];
        a2 += qs[d + 2] * W1[(size_t)(d + 2) * U_SZ + u];
        a3 += qs[d + 3] * W1[(size_t)(d + 3) * U_SZ + u];
    }
    g_A[b * U_SZ + u] = b1[u] + b2[u] + ((a0 + a1) + (a2 + a3));
}

// ---------------------------------------------------------------------------
// Kernel 2 (dominant): fp16 mma.sync GEMM + tanh + Wv partial reduce
// Grid (x=pass 8, y=t-tile 16, z=b 32): pass-fastest launch order makes the
// 8 CTAs sharing one A tile launch-adjacent -> A served from L2, not DRAM.
// CTA: 128 t x 128 u x K=1024; 256 threads = 8 warps (4m x 2n), warp 32x64.
// 16 K-chunks of 64, 3-stage cp.async pipeline, 2 CTAs/SM.
// ---------------------------------------------------------------------------
#define TT 128
#define UC 128
#define KC 64
#define NCHUNK 16
#define OFF_B 16384
#define STAGE 32768
#define EX (3 * STAGE)                    // 98304
#define SMEM_BYTES (EX + 1024 + 1024)     // + sAWv[128] + sred[2][128]

__device__ __forceinline__ void issue_chunk(
    uint32_t sbase, const __half* Abase, const __half* Bbase, int kc, int tid) {
#pragma unroll
    for (int i = 0; i < 4; i++) {
        const int idx = i * 256 + tid;
        const int r = idx >> 3;
        const int c8 = idx & 7;
        const uint32_t sw = (uint32_t)(c8 * 16) ^ (((uint32_t)r & 7u) << 4);
        CP16(sbase + r * 128 + sw, Abase + (size_t)r * D_SZ + kc + c8 * 8);
        CP16(sbase + OFF_B + r * 128 + sw, Bbase + (size_t)r * D_SZ + kc + c8 * 8);
    }
}

__global__ __launch_bounds__(256, 2) void score_mma_kernel(
    const float* __restrict__ Wv) {
    extern __shared__ char sm[];
    const uint32_t base = smem_u32(sm);
    float2* sAWv = (float2*)(sm + EX);
    float(*sred)[TT] = (float(*)[TT])(sm + EX + 1024);

    const int tid = threadIdx.x;
    const int wid = tid >> 5;
    const int lane = tid & 31;
    const int p = blockIdx.x;          // u-pass (fastest -> L2 reuse of A)
    const int t0 = blockIdx.y * TT;
    const int b = blockIdx.z;
    const int u0 = p * UC;

    const int m0 = (wid & 3) * 32;
    const int wn = wid >> 2;
    const int n0 = wn * 64;

    const __half* Abase = g_vh + ((size_t)b * T_SZ + t0) * D_SZ;
    const __half* Bbase = g_W2t + (size_t)u0 * D_SZ;

    if (tid < UC)
        sAWv[tid] = make_float2(g_A[b * U_SZ + u0 + tid], Wv[u0 + tid]);

    // ldmatrix per-lane address components (mapping verified in R4/R5)
    const int mat = lane >> 3, mr = lane & 7;
    const int rowA = m0 + (mat & 1) * 8 + mr;
    const uint32_t aBase0 = rowA * 128, aBase1 = aBase0 + 16 * 128;
    const uint32_t aXor = ((uint32_t)rowA & 7u) << 4;
    const uint32_t aCb = (mat >> 1) * 16;
    const int rowB0 = n0 + (mat >> 1) * 8 + mr;
    const uint32_t bXor = ((uint32_t)rowB0 & 7u) << 4;
    const uint32_t bCb = (mat & 1) * 16;
    uint32_t bBase[4];
#pragma unroll
    for (int ntp = 0; ntp < 4; ntp++)
        bBase[ntp] = OFF_B + (rowB0 + ntp * 16) * 128;

    const int fr = lane >> 2;
    const int fc = (lane & 3) * 2;

    float acc[2][8][4];
#pragma unroll
    for (int mt = 0; mt < 2; mt++)
#pragma unroll
        for (int nt = 0; nt < 8; nt++)
#pragma unroll
            for (int ci = 0; ci < 4; ci++) acc[mt][nt][ci] = 0.f;

    // prologue: chunks 0, 1
    issue_chunk(base, Abase, Bbase, 0, tid);
    CP_COMMIT();
    issue_chunk(base + STAGE, Abase, Bbase, KC, tid);
    CP_COMMIT();

#pragma unroll 1
    for (int c = 0; c < NCHUNK; c++) {
        if (c < NCHUNK - 1) { CP_WAIT(1); } else { CP_WAIT(0); }
        __syncthreads();

        if (c + 2 < NCHUNK) {
            issue_chunk(base + ((c + 2) % 3) * STAGE, Abase, Bbase,
                        (c + 2) * KC, tid);
            CP_COMMIT();
        }

        const uint32_t st = base + (c % 3) * STAGE;
#pragma unroll
        for (int ks = 0; ks < 4; ks++) {
            uint32_t ah[2][4];
            const uint32_t ac = ((uint32_t)(ks * 32) + aCb) ^ aXor;
            LDSM4(ah[0][0], ah[0][1], ah[0][2], ah[0][3], st + aBase0 + ac);
            LDSM4(ah[1][0], ah[1][1], ah[1][2], ah[1][3], st + aBase1 + ac);
            const uint32_t bc = ((uint32_t)(ks * 32) + bCb) ^ bXor;
#pragma unroll
            for (int ntp = 0; ntp < 4; ntp++) {
                uint32_t b0, b1, b2, b3;
                LDSM4(b0, b1, b2, b3, st + bBase[ntp] + bc);
                MMA_F16(acc[0][ntp * 2 + 0], ah[0], b0, b1);
                MMA_F16(acc[0][ntp * 2 + 1], ah[0], b2, b3);
                MMA_F16(acc[1][ntp * 2 + 0], ah[1], b0, b1);
                MMA_F16(acc[1][ntp * 2 + 1], ah[1], b2, b3);
            }
        }
        __syncthreads();   // reads done before this stage is overwritten
    }

    // ---- epilogue: s = sum_u Wv[u] * tanh(D + Aq[u]) over this pass's 128 u
    float s_part[4];
#pragma unroll
    for (int mt = 0; mt < 2; mt++)
#pragma unroll
        for (int h2 = 0; h2 < 2; h2++) {
            float a = 0.f;
#pragma unroll
            for (int nt = 0; nt < 8; nt++) {
                const int cl = n0 + nt * 8 + fc;
                const float2 aw0 = sAWv[cl];
                const float2 aw1 = sAWv[cl + 1];
                a += aw0.y * tanh_approx(acc[mt][nt][h2 * 2 + 0] + aw0.x);
                a += aw1.y * tanh_approx(acc[mt][nt][h2 * 2 + 1] + aw1.x);
            }
            s_part[mt * 2 + h2] = a;
        }

    // reduce quads (lanes sharing a row), then across the 2 n-warps
#pragma unroll
    for (int sp = 0; sp < 4; sp++) {
        float v = s_part[sp];
        v += __shfl_xor_sync(0xffffffffu, v, 1);
        v += __shfl_xor_sync(0xffffffffu, v, 2);
        if ((lane & 3) == 0) sred[wn][m0 + sp * 8 + fr] = v;
    }
    __syncthreads();
    if (tid < TT)
        g_spart[((size_t)p * B_SZ + b) * T_SZ + t0 + tid] =
            sred[0][tid] + sred[1][tid];
}

// ---------------------------------------------------------------------------
// Kernel 3: sum pass-partials + softmax over T per batch -> attention weights
// ---------------------------------------------------------------------------
__global__ __launch_bounds__(256) void softmax_kernel(
    float* __restrict__ wout, const float* __restrict__ bvp) {
    __shared__ float red[256];
    __shared__ float sc[T_SZ];
    const int b = blockIdx.x;
    const int tid = threadIdx.x;
    float* w = wout + b * T_SZ;
    const float bv0 = bvp[0];

    float m = -3.4e38f;
    for (int t = tid; t < T_SZ; t += 256) {
        float s = bv0;
#pragma unroll
        for (int p = 0; p < NPASS; p++)
            s += g_spart[((size_t)p * B_SZ + b) * T_SZ + t];
        sc[t] = s;
        m = fmaxf(m, s);
    }
    red[tid] = m;
    __syncthreads();
    for (int o = 128; o > 0; o >>= 1) {
        if (tid < o) red[tid] = fmaxf(red[tid], red[tid + o]);
        __syncthreads();
    }
    const float mx = red[0];
    __syncthreads();

    float sum = 0.f;
    for (int t = tid; t < T_SZ; t += 256) {
        float e = __expf(sc[t] - mx);
        w[t] = e;
        sum += e;
    }
    red[tid] = sum;
    __syncthreads();
    for (int o = 128; o > 0; o >>= 1) {
        if (tid < o) red[tid] += red[tid + o];
        __syncthreads();
    }
    const float inv = 1.0f / red[0];
    for (int t = tid; t < T_SZ; t += 256) w[t] *= inv;
}

// ---------------------------------------------------------------------------
// Kernel 4/5: context = sum_t w*values (fp16 values, half2, 8-way t-split)
// ---------------------------------------------------------------------------
__global__ __launch_bounds__(256) void context_part_kernel(
    const float* __restrict__ w) {
    __shared__ float wsh[256];
    const int b = blockIdx.y;
    const int z = blockIdx.z;
    const int d2 = blockIdx.x * 256 + threadIdx.x;   // half2 index (0..511)
    const int t0 = z * (T_SZ / CSPLIT);
    if (threadIdx.x < 256) wsh[threadIdx.x] = w[b * T_SZ + t0 + threadIdx.x];
    __syncthreads();
    const __half2* vb = (const __half2*)(g_vh + ((size_t)b * T_SZ + t0) * D_SZ) + d2;
    float2 a0 = {0.f, 0.f}, a1 = {0.f, 0.f};
#pragma unroll 4
    for (int t = 0; t < T_SZ / CSPLIT; t += 2) {
        const float2 v0 = __half22float2(vb[(size_t)(t + 0) * (D_SZ / 2)]);
        const float2 v1 = __half22float2(vb[(size_t)(t + 1) * (D_SZ / 2)]);
        const float w0 = wsh[t + 0], w1 = wsh[t + 1];
        a0.x += w0 * v0.x; a0.y += w0 * v0.y;
        a1.x += w1 * v1.x; a1.y += w1 * v1.y;
    }
    float2 r;
    r.x = a0.x + a1.x;
    r.y = a0.y + a1.y;
    ((float2*)(g_cpart + ((size_t)z * B_SZ + b) * D_SZ))[d2] = r;
}

__global__ void context_reduce_kernel(float* __restrict__ out) {
    const int b = blockIdx.x;
    const int d = threadIdx.x;
    float s = 0.f;
#pragma unroll
    for (int z = 0; z < CSPLIT; z++)
        s += g_cpart[((size_t)z * B_SZ + b) * D_SZ + d];
    out[b * D_SZ + d] = s;
}

// ---------------------------------------------------------------------------
extern "C" void kernel_launch(void* const* d_in, const int* in_sizes, int n_in,
                              void* d_out, int out_size) {
    const float* query  = (const float*)d_in[0];
    const float* values = (const float*)d_in[1];
    const float* W1     = (const float*)d_in[2];
    const float* b1     = (const float*)d_in[3];
    const float* W2     = (const float*)d_in[4];
    const float* b2     = (const float*)d_in[5];
    const float* Wv     = (const float*)d_in[6];
    const float* bv     = (const float*)d_in[7];

    float* out = (float*)d_out;
    float* ctx_out = out;                  // [B, D]
    float* w_out   = out + B_SZ * D_SZ;    // [B, T, 1]

    static int smem_set = 0;
    if (!smem_set) {
        cudaFuncSetAttribute(score_mma_kernel,
                             cudaFuncAttributeMaxDynamicSharedMemorySize, SMEM_BYTES);
        smem_set = 1;
    }

    // launch index 3 = score_mma_kernel (ncu captures index 3 in this harness)
    vprep_kernel<<<32768, 256>>>(values);                            // 0
    w2t_prep_kernel<<<dim3(D_SZ / 32, U_SZ / 32), 256>>>(W2);        // 1
    qproj_kernel<<<dim3(4, B_SZ), 256>>>(query, W1, b1, b2);         // 2
    score_mma_kernel<<<dim3(NPASS, T_SZ / TT, B_SZ), 256, SMEM_BYTES>>>(Wv); // 3
    softmax_kernel<<<B_SZ, 256>>>(w_out, bv);                        // 4
    context_part_kernel<<<dim3(2, B_SZ, CSPLIT), 256>>>(w_out);      // 5
    context_reduce_kernel<<<B_SZ, 1024>>>(ctx_out);                  // 6
}

// round 12
// speedup vs baseline: 8.1309x; 1.0056x over previous
#include <cuda_runtime.h>
#include <cuda_fp16.h>
#include <cstdint>
#include <math.h>

#define B_SZ 32
#define T_SZ 2048
#define D_SZ 1024
#define U_SZ 1024
#define NPASS 8
#define CSPLIT 8

typedef unsigned long long u64;

// ---------------- static device scratch (no runtime allocation) -------------
__device__ float g_A[B_SZ * U_SZ];               // q@W1 + b1 + b2
__device__ float g_spart[NPASS * B_SZ * T_SZ];   // per-pass partial scores
__device__ float g_cpart[CSPLIT * B_SZ * D_SZ];  // context partials
__device__ __half g_W2t[U_SZ * D_SZ];            // W2^T fp16 [u][d]
__device__ __half g_vh[67108864];                // values as fp16 (B*T*D)

// ---------------- PTX helpers ----------------------------------------------
__device__ __forceinline__ uint32_t smem_u32(const void* p) {
    uint32_t a;
    asm("{ .reg .u64 t; cvta.to.shared.u64 t, %1; cvt.u32.u64 %0, t; }"
        : "=r"(a) : "l"(p));
    return a;
}
__device__ __forceinline__ float tanh_approx(float x) {
    float y;
    asm("tanh.approx.f32 %0, %1;" : "=f"(y) : "f"(x));
    return y;
}
#define CP16(s, g) \
    asm volatile("cp.async.cg.shared.global [%0], [%1], 16;" :: "r"(s), "l"(g))
#define CP_COMMIT() asm volatile("cp.async.commit_group;" ::: "memory")
#define CP_WAIT(n) asm volatile("cp.async.wait_group %0;" :: "n"(n) : "memory")
#define LDSM4(R0, R1, R2, R3, A) \
    asm volatile("ldmatrix.sync.aligned.m8n8.x4.shared.b16 {%0,%1,%2,%3}, [%4];" \
                 : "=r"(R0), "=r"(R1), "=r"(R2), "=r"(R3) : "r"(A))
#define MMA_F16(d, a, b0, b1)                                               \
    asm volatile(                                                           \
        "mma.sync.aligned.m16n8k16.row.col.f32.f16.f16.f32 "                \
        "{%0,%1,%2,%3}, {%4,%5,%6,%7}, {%8,%9}, {%0,%1,%2,%3};"             \
        : "+f"((d)[0]), "+f"((d)[1]), "+f"((d)[2]), "+f"((d)[3])            \
        : "r"((a)[0]), "r"((a)[1]), "r"((a)[2]), "r"((a)[3]),               \
          "r"(b0), "r"(b1))

// ---------------------------------------------------------------------------
// Kernel P0: values fp32 -> fp16 (one uint4 = 8 halves per thread)
// ---------------------------------------------------------------------------
__global__ __launch_bounds__(256) void vprep_kernel(const float* __restrict__ v) {
    const size_t i8 = (size_t)blockIdx.x * 256 + threadIdx.x;
    const float4 v0 = ((const float4*)v)[i8 * 2];
    const float4 v1 = ((const float4*)v)[i8 * 2 + 1];
    uint4 o;
    __half2 h;
    h = __floats2half2_rn(v0.x, v0.y); o.x = *(unsigned*)&h;
    h = __floats2half2_rn(v0.z, v0.w); o.y = *(unsigned*)&h;
    h = __floats2half2_rn(v1.x, v1.y); o.z = *(unsigned*)&h;
    h = __floats2half2_rn(v1.z, v1.w); o.w = *(unsigned*)&h;
    ((uint4*)g_vh)[i8] = o;
}

// ---------------------------------------------------------------------------
// Kernel P1: W2 -> transposed fp16 (tiled transpose)
// ---------------------------------------------------------------------------
__global__ __launch_bounds__(256) void w2t_prep_kernel(const float* __restrict__ W2) {
    __shared__ float tile[32][33];
    const int d0 = blockIdx.x * 32, u0 = blockIdx.y * 32;
    const int tx = threadIdx.x & 31, ty = threadIdx.x >> 5;   // 32 x 8
#pragma unroll
    for (int i = 0; i < 4; i++)
        tile[ty * 4 + i][tx] = W2[(size_t)(d0 + ty * 4 + i) * U_SZ + u0 + tx];
    __syncthreads();
#pragma unroll
    for (int i = 0; i < 4; i++) {
        const int u = u0 + ty * 4 + i;
        g_W2t[(size_t)u * D_SZ + d0 + tx] = __float2half_rn(tile[tx][ty * 4 + i]);
    }
}

// ---------------------------------------------------------------------------
// Kernel 1: A[b,u] = q@W1 + b1 + b2   (fp32, exact)
// ---------------------------------------------------------------------------
__global__ __launch_bounds__(256) void qproj_kernel(
    const float* __restrict__ query, const float* __restrict__ W1,
    const float* __restrict__ b1, const float* __restrict__ b2) {
    __shared__ float qs[D_SZ];
    const int b = blockIdx.y;
    const int u = blockIdx.x * 256 + threadIdx.x;
#pragma unroll
    for (int i = 0; i < 4; i++)
        qs[threadIdx.x + i * 256] = query[b * D_SZ + threadIdx.x + i * 256];
    __syncthreads();
    float a0 = 0.f, a1 = 0.f, a2 = 0.f, a3 = 0.f;
#pragma unroll 4
    for (int d = 0; d < D_SZ; d += 4) {
        a0 += qs[d + 0] * W1[(size_t)(d + 0) * U_SZ + u];
        a1 += qs[d + 1] * W1[(size_t)(d + 1) * U_SZ + u];
        a2 += qs[d + 2] * W1[(size_t)(d + 2) * U_SZ + u];
        a3 += qs[d + 3] * W1[(size_t)(d + 3) * U_SZ + u];
    }
    g_A[b * U_SZ + u] = b1[u] + b2[u] + ((a0 + a1) + (a2 + a3));
}

// ---------------------------------------------------------------------------
// Kernel 2 (dominant): fp16 mma.sync GEMM + tanh + Wv partial reduce
// Grid (x=pass 8, y=t-tile 16, z=b 32): pass-fastest order -> A tile served
// from L2 (verified R10: DRAM 43.8% -> 5.8%).
// CTA: 128 t x 128 u x K=1024; 256 threads = 8 warps (4m x 2n), warp 32x64.
// 16 K-chunks of 64, 3-stage cp.async pipeline, ONE __syncthreads per chunk
// (trailing sync removed: chunk c+2 writes stage (c-1)%3, whose readers all
// passed the top-of-iter-c sync before any thread issues the cp.async).
// ---------------------------------------------------------------------------
#define TT 128
#define UC 128
#define KC 64
#define NCHUNK 16
#define OFF_B 16384
#define STAGE 32768
#define EX (3 * STAGE)                    // 98304
#define SMEM_BYTES (EX + 1024 + 1024)     // + sAWv[128] + sred[2][128]

__device__ __forceinline__ void issue_chunk(
    uint32_t sbase, const __half* Abase, const __half* Bbase, int kc, int tid) {
#pragma unroll
    for (int i = 0; i < 4; i++) {
        const int idx = i * 256 + tid;
        const int r = idx >> 3;
        const int c8 = idx & 7;
        const uint32_t sw = (uint32_t)(c8 * 16) ^ (((uint32_t)r & 7u) << 4);
        CP16(sbase + r * 128 + sw, Abase + (size_t)r * D_SZ + kc + c8 * 8);
        CP16(sbase + OFF_B + r * 128 + sw, Bbase + (size_t)r * D_SZ + kc + c8 * 8);
    }
}

__global__ __launch_bounds__(256, 2) void score_mma_kernel(
    const float* __restrict__ Wv) {
    extern __shared__ char sm[];
    const uint32_t base = smem_u32(sm);
    float2* sAWv = (float2*)(sm + EX);
    float(*sred)[TT] = (float(*)[TT])(sm + EX + 1024);

    const int tid = threadIdx.x;
    const int wid = tid >> 5;
    const int lane = tid & 31;
    const int p = blockIdx.x;          // u-pass (fastest -> L2 reuse of A)
    const int t0 = blockIdx.y * TT;
    const int b = blockIdx.z;
    const int u0 = p * UC;

    const int m0 = (wid & 3) * 32;
    const int wn = wid >> 2;
    const int n0 = wn * 64;

    const __half* Abase = g_vh + ((size_t)b * T_SZ + t0) * D_SZ;
    const __half* Bbase = g_W2t + (size_t)u0 * D_SZ;

    if (tid < UC)
        sAWv[tid] = make_float2(g_A[b * U_SZ + u0 + tid], Wv[u0 + tid]);

    // ldmatrix per-lane address components (mapping verified in R4/R5)
    const int mat = lane >> 3, mr = lane & 7;
    const int rowA = m0 + (mat & 1) * 8 + mr;
    const uint32_t aBase0 = rowA * 128, aBase1 = aBase0 + 16 * 128;
    const uint32_t aXor = ((uint32_t)rowA & 7u) << 4;
    const uint32_t aCb = (mat >> 1) * 16;
    const int rowB0 = n0 + (mat >> 1) * 8 + mr;
    const uint32_t bXor = ((uint32_t)rowB0 & 7u) << 4;
    const uint32_t bCb = (mat & 1) * 16;
    uint32_t bBase[4];
#pragma unroll
    for (int ntp = 0; ntp < 4; ntp++)
        bBase[ntp] = OFF_B + (rowB0 + ntp * 16) * 128;

    const int fr = lane >> 2;
    const int fc = (lane & 3) * 2;

    float acc[2][8][4];
#pragma unroll
    for (int mt = 0; mt < 2; mt++)
#pragma unroll
        for (int nt = 0; nt < 8; nt++)
#pragma unroll
            for (int ci = 0; ci < 4; ci++) acc[mt][nt][ci] = 0.f;

    // prologue: chunks 0, 1
    issue_chunk(base, Abase, Bbase, 0, tid);
    CP_COMMIT();
    issue_chunk(base + STAGE, Abase, Bbase, KC, tid);
    CP_COMMIT();

#pragma unroll 1
    for (int c = 0; c < NCHUNK; c++) {
        if (c < NCHUNK - 1) { CP_WAIT(1); } else { CP_WAIT(0); }
        __syncthreads();   // chunk c visible to all; stage (c+2)%3 free to fill

        if (c + 2 < NCHUNK) {
            issue_chunk(base + ((c + 2) % 3) * STAGE, Abase, Bbase,
                        (c + 2) * KC, tid);
            CP_COMMIT();
        }

        const uint32_t st = base + (c % 3) * STAGE;
#pragma unroll
        for (int ks = 0; ks < 4; ks++) {
            uint32_t ah[2][4];
            const uint32_t ac = ((uint32_t)(ks * 32) + aCb) ^ aXor;
            LDSM4(ah[0][0], ah[0][1], ah[0][2], ah[0][3], st + aBase0 + ac);
            LDSM4(ah[1][0], ah[1][1], ah[1][2], ah[1][3], st + aBase1 + ac);
            const uint32_t bc = ((uint32_t)(ks * 32) + bCb) ^ bXor;
#pragma unroll
            for (int ntp = 0; ntp < 4; ntp++) {
                uint32_t b0, b1, b2, b3;
                LDSM4(b0, b1, b2, b3, st + bBase[ntp] + bc);
                MMA_F16(acc[0][ntp * 2 + 0], ah[0], b0, b1);
                MMA_F16(acc[0][ntp * 2 + 1], ah[0], b2, b3);
                MMA_F16(acc[1][ntp * 2 + 0], ah[1], b0, b1);
                MMA_F16(acc[1][ntp * 2 + 1], ah[1], b2, b3);
            }
        }
        // no trailing sync: next overwrite of stage c%3 (chunk c+3) is gated
        // by the top-of-iteration sync of iter c+1.
    }

    // ---- epilogue: s = sum_u Wv[u] * tanh(D + Aq[u]) over this pass's 128 u
    float s_part[4];
#pragma unroll
    for (int mt = 0; mt < 2; mt++)
#pragma unroll
        for (int h2 = 0; h2 < 2; h2++) {
            float a = 0.f;
#pragma unroll
            for (int nt = 0; nt < 8; nt++) {
                const int cl = n0 + nt * 8 + fc;
                const float2 aw0 = sAWv[cl];
                const float2 aw1 = sAWv[cl + 1];
                a += aw0.y * tanh_approx(acc[mt][nt][h2 * 2 + 0] + aw0.x);
                a += aw1.y * tanh_approx(acc[mt][nt][h2 * 2 + 1] + aw1.x);
            }
            s_part[mt * 2 + h2] = a;
        }

    // reduce quads (lanes sharing a row), then across the 2 n-warps
#pragma unroll
    for (int sp = 0; sp < 4; sp++) {
        float v = s_part[sp];
        v += __shfl_xor_sync(0xffffffffu, v, 1);
        v += __shfl_xor_sync(0xffffffffu, v, 2);
        if ((lane & 3) == 0) sred[wn][m0 + sp * 8 + fr] = v;
    }
    __syncthreads();
    if (tid < TT)
        g_spart[((size_t)p * B_SZ + b) * T_SZ + t0 + tid] =
            sred[0][tid] + sred[1][tid];
}

// ---------------------------------------------------------------------------
// Kernel 3: sum pass-partials + softmax over T per batch -> attention weights
// ---------------------------------------------------------------------------
__global__ __launch_bounds__(256) void softmax_kernel(
    float* __restrict__ wout, const float* __restrict__ bvp) {
    __shared__ float red[256];
    __shared__ float sc[T_SZ];
    const int b = blockIdx.x;
    const int tid = threadIdx.x;
    float* w = wout + b * T_SZ;
    const float bv0 = bvp[0];

    float m = -3.4e38f;
    for (int t = tid; t < T_SZ; t += 256) {
        float s = bv0;
#pragma unroll
        for (int p = 0; p < NPASS; p++)
            s += g_spart[((size_t)p * B_SZ + b) * T_SZ + t];
        sc[t] = s;
        m = fmaxf(m, s);
    }
    red[tid] = m;
    __syncthreads();
    for (int o = 128; o > 0; o >>= 1) {
        if (tid < o) red[tid] = fmaxf(red[tid], red[tid + o]);
        __syncthreads();
    }
    const float mx = red[0];
    __syncthreads();

    float sum = 0.f;
    for (int t = tid; t < T_SZ; t += 256) {
        float e = __expf(sc[t] - mx);
        w[t] = e;
        sum += e;
    }
    red[tid] = sum;
    __syncthreads();
    for (int o = 128; o > 0; o >>= 1) {
        if (tid < o) red[tid] += red[tid + o];
        __syncthreads();
    }
    const float inv = 1.0f / red[0];
    for (int t = tid; t < T_SZ; t += 256) w[t] *= inv;
}

// ---------------------------------------------------------------------------
// Kernel 4/5: context = sum_t w*values (fp16 values, half2, 8-way t-split)
// ---------------------------------------------------------------------------
__global__ __launch_bounds__(256) void context_part_kernel(
    const float* __restrict__ w) {
    __shared__ float wsh[256];
    const int b = blockIdx.y;
    const int z = blockIdx.z;
    const int d2 = blockIdx.x * 256 + threadIdx.x;   // half2 index (0..511)
    const int t0 = z * (T_SZ / CSPLIT);
    if (threadIdx.x < 256) wsh[threadIdx.x] = w[b * T_SZ + t0 + threadIdx.x];
    __syncthreads();
    const __half2* vb = (const __half2*)(g_vh + ((size_t)b * T_SZ + t0) * D_SZ) + d2;
    float2 a0 = {0.f, 0.f}, a1 = {0.f, 0.f};
#pragma unroll 4
    for (int t = 0; t < T_SZ / CSPLIT; t += 2) {
        const float2 v0 = __half22float2(vb[(size_t)(t + 0) * (D_SZ / 2)]);
        const float2 v1 = __half22float2(vb[(size_t)(t + 1) * (D_SZ / 2)]);
        const float w0 = wsh[t + 0], w1 = wsh[t + 1];
        a0.x += w0 * v0.x; a0.y += w0 * v0.y;
        a1.x += w1 * v1.x; a1.y += w1 * v1.y;
    }
    float2 r;
    r.x = a0.x + a1.x;
    r.y = a0.y + a1.y;
    ((float2*)(g_cpart + ((size_t)z * B_SZ + b) * D_SZ))[d2] = r;
}

__global__ void context_reduce_kernel(float* __restrict__ out) {
    const int b = blockIdx.x;
    const int d = threadIdx.x;
    float s = 0.f;
#pragma unroll
    for (int z = 0; z < CSPLIT; z++)
        s += g_cpart[((size_t)z * B_SZ + b) * D_SZ + d];
    out[b * D_SZ + d] = s;
}

// ---------------------------------------------------------------------------
extern "C" void kernel_launch(void* const* d_in, const int* in_sizes, int n_in,
                              void* d_out, int out_size) {
    const float* query  = (const float*)d_in[0];
    const float* values = (const float*)d_in[1];
    const float* W1     = (const float*)d_in[2];
    const float* b1     = (const float*)d_in[3];
    const float* W2     = (const float*)d_in[4];
    const float* b2     = (const float*)d_in[5];
    const float* Wv     = (const float*)d_in[6];
    const float* bv     = (const float*)d_in[7];

    float* out = (float*)d_out;
    float* ctx_out = out;                  // [B, D]
    float* w_out   = out + B_SZ * D_SZ;    // [B, T, 1]

    static int smem_set = 0;
    if (!smem_set) {
        cudaFuncSetAttribute(score_mma_kernel,
                             cudaFuncAttributeMaxDynamicSharedMemorySize, SMEM_BYTES);
        smem_set = 1;
    }

    // launch index 3 = score_mma_kernel (ncu captures index 3 in this harness)
    vprep_kernel<<<32768, 256>>>(values);                            // 0
    w2t_prep_kernel<<<dim3(D_SZ / 32, U_SZ / 32), 256>>>(W2);        // 1
    qproj_kernel<<<dim3(4, B_SZ), 256>>>(query, W1, b1, b2);         // 2
    score_mma_kernel<<<dim3(NPASS, T_SZ / TT, B_SZ), 256, SMEM_BYTES>>>(Wv); // 3
    softmax_kernel<<<B_SZ, 256>>>(w_out, bv);                        // 4
    context_part_kernel<<<dim3(2, B_SZ, CSPLIT), 256>>>(w_out);      // 5
    context_reduce_kernel<<<B_SZ, 1024>>>(ctx_out);                  // 6
}